// round 1
// baseline (speedup 1.0000x reference)
#include <cuda_runtime.h>
#include <math.h>

// Problem constants
#define CH    256
#define TDIM  4096
#define BATCH 16
#define TT    64          // time-tile per CTA
#define PADL  8           // (K-1)*dilation

// SMEM strides (floats), padded for 16B alignment + bank spreading
#define XS_STRIDE 76      // TT + PADL = 72, padded
#define WS_STRIDE 68      // 64, padded

#define SMEM_A ((256*XS_STRIDE + 2*64*WS_STRIDE)*4)   // 112,640 B
#define SMEM_B ((256*WS_STRIDE + 64*WS_STRIDE)*4)     //  87,040 B

// Scratch (device globals: allocation-free per harness rules)
__device__ float g_wfg[512*512];                       // packed [filter;gate] x [x(t) ; x(t-8)] weights
__device__ float g_wrs[512*256];                       // packed [res;skip] 1x1 weights
__device__ float g_z[(size_t)BATCH*CH*TDIM];           // gated activations z = tanh(f)*sigmoid(g)

// ---------------------------------------------------------------------------
// Pack weights into GEMM-friendly layouts.
//   W_fg[m][k]: m<256 -> filter out-ch m ; m>=256 -> gate out-ch m-256
//               k<256 -> tap w[o][k][1] (pairs x[t]) ; k>=256 -> tap w[o][k-256][0] (pairs x[t-8])
//   W_rs[m][k]: m<256 -> w_res[m][k] ; m>=256 -> w_skip[m-256][k]
// ---------------------------------------------------------------------------
__global__ void pack_weights_kernel(const float* __restrict__ wf, const float* __restrict__ wg,
                                    const float* __restrict__ wr, const float* __restrict__ wsk)
{
    int idx = blockIdx.x * blockDim.x + threadIdx.x;
    if (idx < 512*512) {
        int m = idx >> 9, k = idx & 511;
        const float* w = (m < 256) ? wf : wg;
        int o = m & 255;
        g_wfg[idx] = (k < 256) ? w[o*512 + k*2 + 1] : w[o*512 + (k - 256)*2];
    }
    if (idx < 512*256) {
        int m = idx >> 8, k = idx & 255;
        g_wrs[idx] = (m < 256) ? wr[m*256 + k] : wsk[(m - 256)*256 + k];
    }
}

// ---------------------------------------------------------------------------
// Kernel A: FG = W_fg * U, fused activation -> z  (GEMM1, K=512)
// CTA = (t-tile of 64, batch). Thread tile: 4 m (filter) + 4 m (gate) x 4 n.
// ---------------------------------------------------------------------------
__global__ void __launch_bounds__(256) wavenet_fg_kernel(
    const float* __restrict__ x, const float* __restrict__ bf, const float* __restrict__ bg)
{
    extern __shared__ float sm[];
    float* xs  = sm;                         // [256][XS_STRIDE] : x[c][t0-8 .. t0+63]
    float* wsF = sm + 256*XS_STRIDE;         // [64 k][WS_STRIDE r] (k-major, transposed)
    float* wsG = wsF + 64*WS_STRIDE;

    const int b   = blockIdx.y;
    const int t0  = blockIdx.x * TT;
    const int tid = threadIdx.x;
    const float* xb = x + (size_t)b * CH * TDIM;

    // Load x tile (with left halo of 8, zero before t=0)
    for (int idx = tid; idx < 256*(TT + PADL); idx += 256) {
        int c = idx / (TT + PADL);
        int j = idx - c * (TT + PADL);
        int t = t0 - PADL + j;
        xs[c*XS_STRIDE + j] = (t >= 0) ? xb[c*TDIM + t] : 0.0f;
    }

    const int tn = tid & 15;                 // n tile: 4 consecutive t
    const int tm = tid >> 4;                 // m tile: 4 consecutive out-ch rows

    for (int mc = 0; mc < 4; mc++) {         // 4 chunks of 64 output channels
        float accF[4][4], accG[4][4];
        #pragma unroll
        for (int i = 0; i < 4; i++)
            #pragma unroll
            for (int j = 0; j < 4; j++) { accF[i][j] = 0.0f; accG[i][j] = 0.0f; }

        for (int kc = 0; kc < 8; kc++) {     // K=512 in chunks of 64
            __syncthreads();
            const float* srcF = g_wfg + (mc*64)*512        + kc*64;
            const float* srcG = g_wfg + (256 + mc*64)*512  + kc*64;
            for (int idx = tid; idx < 64*64; idx += 256) {
                int r = idx >> 6, kk = idx & 63;
                wsF[kk*WS_STRIDE + r] = srcF[r*512 + kk];
                wsG[kk*WS_STRIDE + r] = srcG[r*512 + kk];
            }
            __syncthreads();

            // k<256 pairs x[t] (offset +8 in halo tile); k>=256 pairs x[t-8] (offset 0)
            const float* ub = (kc < 4) ? (xs + (kc*64)*XS_STRIDE     + PADL + tn*4)
                                       : (xs + ((kc - 4)*64)*XS_STRIDE      + tn*4);
            const float* wfp = wsF + tm*4;
            const float* wgp = wsG + tm*4;

            #pragma unroll 8
            for (int kk = 0; kk < 64; kk++) {
                float4 u4 = *(const float4*)(ub  + kk*XS_STRIDE);
                float4 f4 = *(const float4*)(wfp + kk*WS_STRIDE);
                float4 g4 = *(const float4*)(wgp + kk*WS_STRIDE);
                const float uu[4] = {u4.x, u4.y, u4.z, u4.w};
                const float fw[4] = {f4.x, f4.y, f4.z, f4.w};
                const float gw[4] = {g4.x, g4.y, g4.z, g4.w};
                #pragma unroll
                for (int i = 0; i < 4; i++)
                    #pragma unroll
                    for (int j = 0; j < 4; j++) {
                        accF[i][j] = fmaf(fw[i], uu[j], accF[i][j]);
                        accG[i][j] = fmaf(gw[i], uu[j], accG[i][j]);
                    }
            }
        }

        // Activation + store z tile (coalesced float4)
        float* zb = g_z + (size_t)b * CH * TDIM + t0 + tn*4;
        #pragma unroll
        for (int i = 0; i < 4; i++) {
            int m = mc*64 + tm*4 + i;
            float bfv = bf[m], bgv = bg[m];
            float4 zv;
            float* zp = (float*)&zv;
            #pragma unroll
            for (int j = 0; j < 4; j++) {
                float fv = tanhf(accF[i][j] + bfv);
                float gv = accG[i][j] + bgv;
                float sv = 1.0f / (1.0f + __expf(-gv));
                zp[j] = fv * sv;
            }
            *(float4*)(zb + (size_t)m * TDIM) = zv;
        }
    }
}

// ---------------------------------------------------------------------------
// Kernel B: [res;skip] = W_rs * Z, epilogue adds bias (+x for residual) (GEMM2, K=256)
// ---------------------------------------------------------------------------
__global__ void __launch_bounds__(256) wavenet_out_kernel(
    const float* __restrict__ x, const float* __restrict__ br, const float* __restrict__ bs,
    float* __restrict__ out)
{
    extern __shared__ float sm[];
    float* zs = sm;                          // [256][WS_STRIDE]
    float* ws = sm + 256*WS_STRIDE;          // [64 k][WS_STRIDE r]

    const int b   = blockIdx.y;
    const int t0  = blockIdx.x * TT;
    const int tid = threadIdx.x;

    const float* zb = g_z + (size_t)b * CH * TDIM + t0;
    for (int idx = tid; idx < 256*(TT/4); idx += 256) {
        int c = idx >> 4, q = idx & 15;
        *(float4*)(zs + c*WS_STRIDE + q*4) = *(const float4*)(zb + (size_t)c*TDIM + q*4);
    }

    const int tn = tid & 15;
    const int tm = tid >> 4;

    for (int mch = 0; mch < 8; mch++) {      // 8 chunks of 64 output rows (res 0..3, skip 4..7)
        float acc[4][4];
        #pragma unroll
        for (int i = 0; i < 4; i++)
            #pragma unroll
            for (int j = 0; j < 4; j++) acc[i][j] = 0.0f;

        for (int kc = 0; kc < 4; kc++) {     // K=256 in chunks of 64
            __syncthreads();
            const float* src = g_wrs + (mch*64)*256 + kc*64;
            for (int idx = tid; idx < 64*64; idx += 256) {
                int r = idx >> 6, kk = idx & 63;
                ws[kk*WS_STRIDE + r] = src[r*256 + kk];
            }
            __syncthreads();

            const float* up = zs + (kc*64)*WS_STRIDE + tn*4;
            const float* wp = ws + tm*4;
            #pragma unroll 8
            for (int kk = 0; kk < 64; kk++) {
                float4 u4 = *(const float4*)(up + kk*WS_STRIDE);
                float4 w4 = *(const float4*)(wp + kk*WS_STRIDE);
                const float uu[4] = {u4.x, u4.y, u4.z, u4.w};
                const float wwv[4] = {w4.x, w4.y, w4.z, w4.w};
                #pragma unroll
                for (int i = 0; i < 4; i++)
                    #pragma unroll
                    for (int j = 0; j < 4; j++)
                        acc[i][j] = fmaf(wwv[i], uu[j], acc[i][j]);
            }
        }

        const size_t tbase = (size_t)t0 + tn*4;
        #pragma unroll
        for (int i = 0; i < 4; i++) {
            int m = mch*64 + tm*4 + i;
            float4 v = make_float4(acc[i][0], acc[i][1], acc[i][2], acc[i][3]);
            if (m < 256) {   // residual = x + conv1x1_res(z)  (uniform per chunk, no divergence)
                float bias = br[m];
                const float4 xv = *(const float4*)(x + ((size_t)(b*CH + m))*TDIM + tbase);
                v.x += xv.x + bias; v.y += xv.y + bias; v.z += xv.z + bias; v.w += xv.w + bias;
                *(float4*)(out + ((size_t)(b*CH + m))*TDIM + tbase) = v;
            } else {         // skip = conv1x1_skip(z)
                float bias = bs[m - 256];
                v.x += bias; v.y += bias; v.z += bias; v.w += bias;
                *(float4*)(out + (size_t)BATCH*CH*TDIM
                               + ((size_t)(b*CH + (m - 256)))*TDIM + tbase) = v;
            }
        }
    }
}

// ---------------------------------------------------------------------------
extern "C" void kernel_launch(void* const* d_in, const int* in_sizes, int n_in,
                              void* d_out, int out_size)
{
    const float* x   = (const float*)d_in[0];
    const float* wf  = (const float*)d_in[1];
    const float* bf  = (const float*)d_in[2];
    const float* wg  = (const float*)d_in[3];
    const float* bg  = (const float*)d_in[4];
    const float* wr  = (const float*)d_in[5];
    const float* br  = (const float*)d_in[6];
    const float* wsk = (const float*)d_in[7];
    const float* bsk = (const float*)d_in[8];
    float* out = (float*)d_out;

    cudaFuncSetAttribute(wavenet_fg_kernel,  cudaFuncAttributeMaxDynamicSharedMemorySize, SMEM_A);
    cudaFuncSetAttribute(wavenet_out_kernel, cudaFuncAttributeMaxDynamicSharedMemorySize, SMEM_B);

    pack_weights_kernel<<<(512*512 + 255)/256, 256>>>(wf, wg, wr, wsk);

    dim3 grid(TDIM/TT, BATCH);
    wavenet_fg_kernel <<<grid, 256, SMEM_A>>>(x, bf, bg);
    wavenet_out_kernel<<<grid, 256, SMEM_B>>>(x, br, bsk, out);
}

// round 2
// speedup vs baseline: 1.0002x; 1.0002x over previous
#include <cuda_runtime.h>
#include <math.h>

// Problem constants
#define CH    256
#define TDIM  4096
#define BATCH 16
#define TT    64          // time-tile per CTA
#define PADL  8           // (K-1)*dilation

// SMEM strides (floats), padded for 16B alignment + bank spreading
#define XS_STRIDE 76      // TT + PADL = 72, padded
#define WS_STRIDE 68      // 64, padded

#define SMEM_A ((256*XS_STRIDE + 2*64*WS_STRIDE)*4)   // 112,640 B
#define SMEM_B ((256*WS_STRIDE + 64*WS_STRIDE)*4)     //  87,040 B

// Scratch (device globals: allocation-free per harness rules)
__device__ float g_wfg[512*512];                       // packed [filter;gate] x [x(t) ; x(t-8)] weights
__device__ float g_wrs[512*256];                       // packed [res;skip] 1x1 weights
__device__ float g_z[(size_t)BATCH*CH*TDIM];           // gated activations z = tanh(f)*sigmoid(g)

// ---------------------------------------------------------------------------
// Pack weights into GEMM-friendly layouts.
//   W_fg[m][k]: m<256 -> filter out-ch m ; m>=256 -> gate out-ch m-256
//               k<256 -> tap w[o][k][1] (pairs x[t]) ; k>=256 -> tap w[o][k-256][0] (pairs x[t-8])
//   W_rs[m][k]: m<256 -> w_res[m][k] ; m>=256 -> w_skip[m-256][k]
// ---------------------------------------------------------------------------
__global__ void pack_weights_kernel(const float* __restrict__ wf, const float* __restrict__ wg,
                                    const float* __restrict__ wr, const float* __restrict__ wsk)
{
    int idx = blockIdx.x * blockDim.x + threadIdx.x;
    if (idx < 512*512) {
        int m = idx >> 9, k = idx & 511;
        const float* w = (m < 256) ? wf : wg;
        int o = m & 255;
        g_wfg[idx] = (k < 256) ? w[o*512 + k*2 + 1] : w[o*512 + (k - 256)*2];
    }
    if (idx < 512*256) {
        int m = idx >> 8, k = idx & 255;
        g_wrs[idx] = (m < 256) ? wr[m*256 + k] : wsk[(m - 256)*256 + k];
    }
}

// ---------------------------------------------------------------------------
// Kernel A: FG = W_fg * U, fused activation -> z  (GEMM1, K=512)
// CTA = (t-tile of 64, batch). Thread tile: 4 m (filter) + 4 m (gate) x 4 n.
// ---------------------------------------------------------------------------
__global__ void __launch_bounds__(256) wavenet_fg_kernel(
    const float* __restrict__ x, const float* __restrict__ bf, const float* __restrict__ bg)
{
    extern __shared__ float sm[];
    float* xs  = sm;                         // [256][XS_STRIDE] : x[c][t0-8 .. t0+63]
    float* wsF = sm + 256*XS_STRIDE;         // [64 k][WS_STRIDE r] (k-major, transposed)
    float* wsG = wsF + 64*WS_STRIDE;

    const int b   = blockIdx.y;
    const int t0  = blockIdx.x * TT;
    const int tid = threadIdx.x;
    const float* xb = x + (size_t)b * CH * TDIM;

    // Load x tile (with left halo of 8, zero before t=0)
    for (int idx = tid; idx < 256*(TT + PADL); idx += 256) {
        int c = idx / (TT + PADL);
        int j = idx - c * (TT + PADL);
        int t = t0 - PADL + j;
        xs[c*XS_STRIDE + j] = (t >= 0) ? xb[c*TDIM + t] : 0.0f;
    }

    const int tn = tid & 15;                 // n tile: 4 consecutive t
    const int tm = tid >> 4;                 // m tile: 4 consecutive out-ch rows

    for (int mc = 0; mc < 4; mc++) {         // 4 chunks of 64 output channels
        float accF[4][4], accG[4][4];
        #pragma unroll
        for (int i = 0; i < 4; i++)
            #pragma unroll
            for (int j = 0; j < 4; j++) { accF[i][j] = 0.0f; accG[i][j] = 0.0f; }

        for (int kc = 0; kc < 8; kc++) {     // K=512 in chunks of 64
            __syncthreads();
            const float* srcF = g_wfg + (mc*64)*512        + kc*64;
            const float* srcG = g_wfg + (256 + mc*64)*512  + kc*64;
            for (int idx = tid; idx < 64*64; idx += 256) {
                int r = idx >> 6, kk = idx & 63;
                wsF[kk*WS_STRIDE + r] = srcF[r*512 + kk];
                wsG[kk*WS_STRIDE + r] = srcG[r*512 + kk];
            }
            __syncthreads();

            // k<256 pairs x[t] (offset +8 in halo tile); k>=256 pairs x[t-8] (offset 0)
            const float* ub = (kc < 4) ? (xs + (kc*64)*XS_STRIDE     + PADL + tn*4)
                                       : (xs + ((kc - 4)*64)*XS_STRIDE      + tn*4);
            const float* wfp = wsF + tm*4;
            const float* wgp = wsG + tm*4;

            #pragma unroll 8
            for (int kk = 0; kk < 64; kk++) {
                float4 u4 = *(const float4*)(ub  + kk*XS_STRIDE);
                float4 f4 = *(const float4*)(wfp + kk*WS_STRIDE);
                float4 g4 = *(const float4*)(wgp + kk*WS_STRIDE);
                const float uu[4] = {u4.x, u4.y, u4.z, u4.w};
                const float fw[4] = {f4.x, f4.y, f4.z, f4.w};
                const float gw[4] = {g4.x, g4.y, g4.z, g4.w};
                #pragma unroll
                for (int i = 0; i < 4; i++)
                    #pragma unroll
                    for (int j = 0; j < 4; j++) {
                        accF[i][j] = fmaf(fw[i], uu[j], accF[i][j]);
                        accG[i][j] = fmaf(gw[i], uu[j], accG[i][j]);
                    }
            }
        }

        // Activation + store z tile (coalesced float4)
        float* zb = g_z + (size_t)b * CH * TDIM + t0 + tn*4;
        #pragma unroll
        for (int i = 0; i < 4; i++) {
            int m = mc*64 + tm*4 + i;
            float bfv = bf[m], bgv = bg[m];
            float4 zv;
            float* zp = (float*)&zv;
            #pragma unroll
            for (int j = 0; j < 4; j++) {
                float fv = tanhf(accF[i][j] + bfv);
                float gv = accG[i][j] + bgv;
                float sv = 1.0f / (1.0f + __expf(-gv));
                zp[j] = fv * sv;
            }
            *(float4*)(zb + (size_t)m * TDIM) = zv;
        }
    }
}

// ---------------------------------------------------------------------------
// Kernel B: [res;skip] = W_rs * Z, epilogue adds bias (+x for residual) (GEMM2, K=256)
// ---------------------------------------------------------------------------
__global__ void __launch_bounds__(256) wavenet_out_kernel(
    const float* __restrict__ x, const float* __restrict__ br, const float* __restrict__ bs,
    float* __restrict__ out)
{
    extern __shared__ float sm[];
    float* zs = sm;                          // [256][WS_STRIDE]
    float* ws = sm + 256*WS_STRIDE;          // [64 k][WS_STRIDE r]

    const int b   = blockIdx.y;
    const int t0  = blockIdx.x * TT;
    const int tid = threadIdx.x;

    const float* zb = g_z + (size_t)b * CH * TDIM + t0;
    for (int idx = tid; idx < 256*(TT/4); idx += 256) {
        int c = idx >> 4, q = idx & 15;
        *(float4*)(zs + c*WS_STRIDE + q*4) = *(const float4*)(zb + (size_t)c*TDIM + q*4);
    }

    const int tn = tid & 15;
    const int tm = tid >> 4;

    for (int mch = 0; mch < 8; mch++) {      // 8 chunks of 64 output rows (res 0..3, skip 4..7)
        float acc[4][4];
        #pragma unroll
        for (int i = 0; i < 4; i++)
            #pragma unroll
            for (int j = 0; j < 4; j++) acc[i][j] = 0.0f;

        for (int kc = 0; kc < 4; kc++) {     // K=256 in chunks of 64
            __syncthreads();
            const float* src = g_wrs + (mch*64)*256 + kc*64;
            for (int idx = tid; idx < 64*64; idx += 256) {
                int r = idx >> 6, kk = idx & 63;
                ws[kk*WS_STRIDE + r] = src[r*256 + kk];
            }
            __syncthreads();

            const float* up = zs + (kc*64)*WS_STRIDE + tn*4;
            const float* wp = ws + tm*4;
            #pragma unroll 8
            for (int kk = 0; kk < 64; kk++) {
                float4 u4 = *(const float4*)(up + kk*WS_STRIDE);
                float4 w4 = *(const float4*)(wp + kk*WS_STRIDE);
                const float uu[4] = {u4.x, u4.y, u4.z, u4.w};
                const float wwv[4] = {w4.x, w4.y, w4.z, w4.w};
                #pragma unroll
                for (int i = 0; i < 4; i++)
                    #pragma unroll
                    for (int j = 0; j < 4; j++)
                        acc[i][j] = fmaf(wwv[i], uu[j], acc[i][j]);
            }
        }

        const size_t tbase = (size_t)t0 + tn*4;
        #pragma unroll
        for (int i = 0; i < 4; i++) {
            int m = mch*64 + tm*4 + i;
            float4 v = make_float4(acc[i][0], acc[i][1], acc[i][2], acc[i][3]);
            if (m < 256) {   // residual = x + conv1x1_res(z)  (uniform per chunk, no divergence)
                float bias = br[m];
                const float4 xv = *(const float4*)(x + ((size_t)(b*CH + m))*TDIM + tbase);
                v.x += xv.x + bias; v.y += xv.y + bias; v.z += xv.z + bias; v.w += xv.w + bias;
                *(float4*)(out + ((size_t)(b*CH + m))*TDIM + tbase) = v;
            } else {         // skip = conv1x1_skip(z)
                float bias = bs[m - 256];
                v.x += bias; v.y += bias; v.z += bias; v.w += bias;
                *(float4*)(out + (size_t)BATCH*CH*TDIM
                               + ((size_t)(b*CH + (m - 256)))*TDIM + tbase) = v;
            }
        }
    }
}

// ---------------------------------------------------------------------------
extern "C" void kernel_launch(void* const* d_in, const int* in_sizes, int n_in,
                              void* d_out, int out_size)
{
    const float* x   = (const float*)d_in[0];
    const float* wf  = (const float*)d_in[1];
    const float* bf  = (const float*)d_in[2];
    const float* wg  = (const float*)d_in[3];
    const float* bg  = (const float*)d_in[4];
    const float* wr  = (const float*)d_in[5];
    const float* br  = (const float*)d_in[6];
    const float* wsk = (const float*)d_in[7];
    const float* bsk = (const float*)d_in[8];
    float* out = (float*)d_out;

    cudaFuncSetAttribute(wavenet_fg_kernel,  cudaFuncAttributeMaxDynamicSharedMemorySize, SMEM_A);
    cudaFuncSetAttribute(wavenet_out_kernel, cudaFuncAttributeMaxDynamicSharedMemorySize, SMEM_B);

    pack_weights_kernel<<<(512*512 + 255)/256, 256>>>(wf, wg, wr, wsk);

    dim3 grid(TDIM/TT, BATCH);
    wavenet_fg_kernel <<<grid, 256, SMEM_A>>>(x, bf, bg);
    wavenet_out_kernel<<<grid, 256, SMEM_B>>>(x, br, bsk, out);
}

// round 4
// speedup vs baseline: 3.0826x; 3.0821x over previous
#include <cuda_runtime.h>
#include <cuda_bf16.h>
#include <cstdint>
#include <math.h>

#define CHN 256
#define TDIM 4096
#define BATCH 16
#define SKIPOFF ((size_t)BATCH*CHN*TDIM)

// bf16 hi/lo planes (device globals: allocation-free)
__device__ __nv_bfloat16 g_xhi[(size_t)BATCH*4104*CHN];
__device__ __nv_bfloat16 g_xlo[(size_t)BATCH*4104*CHN];
__device__ __nv_bfloat16 g_zhi[(size_t)BATCH*TDIM*CHN];
__device__ __nv_bfloat16 g_zlo[(size_t)BATCH*TDIM*CHN];
__device__ __nv_bfloat16 g_w1hi[4*128*512];
__device__ __nv_bfloat16 g_w1lo[4*128*512];
__device__ __nv_bfloat16 g_w2hi[4*128*256];
__device__ __nv_bfloat16 g_w2lo[4*128*256];

// ---------------- helpers ----------------
__device__ __forceinline__ uint32_t smem_u32(const void* p) {
    uint32_t a; asm("{ .reg .u64 t; cvta.to.shared.u64 t, %1; cvt.u32.u64 %0, t; }" : "=r"(a) : "l"(p));
    return a;
}
__device__ __forceinline__ void cp16(uint32_t d, const void* s) {
    asm volatile("cp.async.cg.shared.global [%0], [%1], 16;" :: "r"(d), "l"(s));
}
__device__ __forceinline__ void ldmx4(uint32_t* r, uint32_t a) {
    asm volatile("ldmatrix.sync.aligned.m8n8.x4.shared.b16 {%0,%1,%2,%3}, [%4];"
        : "=r"(r[0]), "=r"(r[1]), "=r"(r[2]), "=r"(r[3]) : "r"(a));
}
__device__ __forceinline__ void mma_bf(float* d, const uint32_t* a, const uint32_t* b) {
    asm volatile("mma.sync.aligned.m16n8k16.row.col.f32.bf16.bf16.f32 "
        "{%0,%1,%2,%3}, {%4,%5,%6,%7}, {%8,%9}, {%0,%1,%2,%3};"
        : "+f"(d[0]), "+f"(d[1]), "+f"(d[2]), "+f"(d[3])
        : "r"(a[0]), "r"(a[1]), "r"(a[2]), "r"(a[3]), "r"(b[0]), "r"(b[1]));
}
__device__ __forceinline__ uint32_t pack_hl(float v0, float v1, uint32_t& lopack) {
    __nv_bfloat16 h0 = __float2bfloat16(v0), h1 = __float2bfloat16(v1);
    __nv_bfloat16 l0 = __float2bfloat16(v0 - __bfloat162float(h0));
    __nv_bfloat16 l1 = __float2bfloat16(v1 - __bfloat162float(h1));
    lopack = ((uint32_t)__bfloat16_as_ushort(l1) << 16) | __bfloat16_as_ushort(l0);
    return ((uint32_t)__bfloat16_as_ushort(h1) << 16) | __bfloat16_as_ushort(h0);
}

// ---------------------------------------------------------------------------
// Pack weights: g_w1[nb][n'][k]: n'<64 -> filter ch nb*64+n', n'>=64 -> gate;
//   k<256 -> tap1 (pairs x[t]), k>=256 -> tap0 (pairs x[t-8]); c = k&255.
// g_w2[nb][n'][k]: n'<64 -> res, else skip; k = channel.
// ---------------------------------------------------------------------------
__global__ void pack_w_kernel(const float* __restrict__ wf, const float* __restrict__ wg,
                              const float* __restrict__ wr, const float* __restrict__ wsk)
{
    int idx = blockIdx.x * blockDim.x + threadIdx.x;
    float v; __nv_bfloat16 *dh, *dl;
    if (idx < 262144) {
        int nb = idx >> 16, np = (idx >> 9) & 127, k = idx & 511;
        int o = nb * 64 + (np & 63), c = k & 255;
        const float* w = (np < 64) ? wf : wg;
        v = w[o * 512 + c * 2 + ((k < 256) ? 1 : 0)];
        dh = g_w1hi + idx; dl = g_w1lo + idx;
    } else if (idx < 393216) {
        int j = idx - 262144;
        int nb = j >> 15, np = (j >> 8) & 127, k = j & 255;
        int o = nb * 64 + (np & 63);
        v = (np < 64) ? wr[o * 256 + k] : wsk[o * 256 + k];
        dh = g_w2hi + j; dl = g_w2lo + j;
    } else return;
    __nv_bfloat16 h = __float2bfloat16(v);
    *dh = h; *dl = __float2bfloat16(v - __bfloat162float(h));
}

// ---------------------------------------------------------------------------
// Pack x -> [b][r=t+8][256] hi/lo planes (rows 0-7 zero). grid(64,4,16).
// ---------------------------------------------------------------------------
__global__ void pack_x_kernel(const float* __restrict__ x)
{
    __shared__ float st[64][65];
    int tc = blockIdx.x, cc = blockIdx.y, b = blockIdx.z, tid = threadIdx.x;
    for (int i = tid; i < 64 * 16; i += 256) {
        int c = i >> 4, q = i & 15;
        float4 v = *(const float4*)(x + ((size_t)(b * CHN + cc * 64 + c)) * TDIM + tc * 64 + q * 4);
        st[q*4+0][c] = v.x; st[q*4+1][c] = v.y; st[q*4+2][c] = v.z; st[q*4+3][c] = v.w;
    }
    __syncthreads();
    for (int i = tid; i < 64 * 32; i += 256) {
        int r = i >> 5, cp = (i & 31) * 2;
        uint32_t lp, hp = pack_hl(st[r][cp], st[r][cp + 1], lp);
        size_t go = ((size_t)b * 4104 + tc * 64 + 8 + r) * CHN + cc * 64 + cp;
        *(uint32_t*)(g_xhi + go) = hp;
        *(uint32_t*)(g_xlo + go) = lp;
    }
    if (tc == 0)
        for (int i = tid; i < 8 * 32; i += 256) {
            int r = i >> 5, cp = (i & 31) * 2;
            size_t go = ((size_t)b * 4104 + r) * CHN + cc * 64 + cp;
            *(uint32_t*)(g_xhi + go) = 0;
            *(uint32_t*)(g_xlo + go) = 0;
        }
}

// ---------------------------------------------------------------------------
// GEMM: C[128 t][128 n] = A[t][K] * B[n][K]^T, 3-pass bf16 split, fused epilogue.
// PHASE 1: A=x image, K=512, epilogue tanh*sigmoid -> z planes.
// PHASE 2: A=z planes, K=256, epilogue bias (+x for res) -> out.
// Warps: 8 (2m x 4n), warp tile 64x32. Stages: 2 x 40960B. smem 81920B.
// ---------------------------------------------------------------------------
template<int PHASE>
__global__ void __launch_bounds__(256) gemm_tc(
    const float* __restrict__ x, const float* __restrict__ b0v,
    const float* __restrict__ b1v, float* __restrict__ out)
{
    extern __shared__ unsigned char smraw[];
    const uint32_t sb = smem_u32(smraw);
    const int tid = threadIdx.x, lane = tid & 31, wid = tid >> 5;
    const int wm = wid & 1, wn = wid >> 1;
    const int tt = blockIdx.x, nb = blockIdx.y, b = blockIdx.z;
    const int t0 = tt * 128;
    const int NK  = (PHASE == 1) ? 16 : 8;
    const int KST = (PHASE == 1) ? 512 : 256;

    const __nv_bfloat16* Ahi = (PHASE == 1) ? g_xhi + (size_t)b * 4104 * CHN
                                            : g_zhi + (size_t)b * TDIM * CHN;
    const __nv_bfloat16* Alo = (PHASE == 1) ? g_xlo + (size_t)b * 4104 * CHN
                                            : g_zlo + (size_t)b * TDIM * CHN;
    const __nv_bfloat16* Bhi = (PHASE == 1) ? g_w1hi + nb * 128 * 512 : g_w2hi + nb * 128 * 256;
    const __nv_bfloat16* Blo = (PHASE == 1) ? g_w1lo + nb * 128 * 512 : g_w2lo + nb * 128 * 256;

    float acc[4][4][4];
    #pragma unroll
    for (int mi = 0; mi < 4; mi++)
        #pragma unroll
        for (int ni = 0; ni < 4; ni++)
            #pragma unroll
            for (int j = 0; j < 4; j++) acc[mi][ni][j] = 0.0f;

    // ---- stage loader ----
    auto load_stage = [&](int kc, int stg) {
        int koff = (PHASE == 1 && kc < 8) ? 8 : 0;
        int acol = (PHASE == 1) ? (kc & 7) * 32 : kc * 32;
        uint32_t sbase = sb + stg * 40960;
        #pragma unroll
        for (int i = 0; i < 4; i++) {
            int idx = tid + i * 256;
            int pl = idx >> 9, r = (idx >> 2) & 127, seg = idx & 3;
            const __nv_bfloat16* asrc = (pl ? Alo : Ahi) + (size_t)(t0 + r + koff) * CHN + acol + seg * 8;
            cp16(sbase + pl * 10240 + r * 80 + seg * 16, asrc);
            const __nv_bfloat16* bsrc = (pl ? Blo : Bhi) + (size_t)r * KST + kc * 32 + seg * 8;
            cp16(sbase + 20480 + pl * 10240 + r * 80 + seg * 16, bsrc);
        }
        asm volatile("cp.async.commit_group;" ::: "memory");
    };

    load_stage(0, 0);
    load_stage(1, 1);

    for (int kc = 0; kc < NK; kc++) {
        if (kc < NK - 1) asm volatile("cp.async.wait_group 1;" ::: "memory");
        else             asm volatile("cp.async.wait_group 0;" ::: "memory");
        __syncthreads();

        const uint32_t abase = sb + (kc & 1) * 40960;
        const uint32_t bbase = abase + 20480;
        #pragma unroll
        for (int ks = 0; ks < 2; ks++) {
            uint32_t ah[4][4], al[4][4], bh[4][2], bl[4][2];
            const int arow = lane & 15, acoll = ks * 16 + (lane >> 4) * 8;
            #pragma unroll
            for (int mi = 0; mi < 4; mi++) {
                uint32_t ad = abase + (wm * 64 + mi * 16 + arow) * 80 + acoll * 2;
                ldmx4(ah[mi], ad);
                ldmx4(al[mi], ad + 10240);
            }
            const int brow = (lane & 7) + ((lane >> 4) << 3);
            const int bcol = ks * 16 + ((lane >> 3) & 1) * 8;
            #pragma unroll
            for (int ni2 = 0; ni2 < 2; ni2++) {
                uint32_t bd = bbase + (wn * 32 + ni2 * 16 + brow) * 80 + bcol * 2;
                uint32_t t4[4];
                ldmx4(t4, bd);
                bh[ni2*2][0] = t4[0]; bh[ni2*2][1] = t4[1];
                bh[ni2*2+1][0] = t4[2]; bh[ni2*2+1][1] = t4[3];
                ldmx4(t4, bd + 10240);
                bl[ni2*2][0] = t4[0]; bl[ni2*2][1] = t4[1];
                bl[ni2*2+1][0] = t4[2]; bl[ni2*2+1][1] = t4[3];
            }
            #pragma unroll
            for (int mi = 0; mi < 4; mi++)
                #pragma unroll
                for (int ni = 0; ni < 4; ni++) {
                    mma_bf(acc[mi][ni], ah[mi], bh[ni]);
                    mma_bf(acc[mi][ni], ah[mi], bl[ni]);
                    mma_bf(acc[mi][ni], al[mi], bh[ni]);
                }
        }
        __syncthreads();
        if (kc + 2 < NK) load_stage(kc + 2, kc & 1);
    }
    __syncthreads();

    // ---- stage C through smem [128 n][132 m] ----
    float* Cs = (float*)smraw;
    {
        const int tr = lane >> 2, tc4 = (lane & 3) * 2;
        #pragma unroll
        for (int mi = 0; mi < 4; mi++)
            #pragma unroll
            for (int ni = 0; ni < 4; ni++) {
                int n0 = wn * 32 + ni * 8 + tc4;
                int m0 = wm * 64 + mi * 16 + tr;
                Cs[n0 * 132 + m0]           = acc[mi][ni][0];
                Cs[(n0 + 1) * 132 + m0]     = acc[mi][ni][1];
                Cs[n0 * 132 + m0 + 8]       = acc[mi][ni][2];
                Cs[(n0 + 1) * 132 + m0 + 8] = acc[mi][ni][3];
            }
    }
    __syncthreads();

    if (PHASE == 1) {
        for (int i = tid; i < 128 * 32; i += 256) {
            int m = i >> 5, cp = (i & 31) * 2;
            float f0 = Cs[cp * 132 + m]       + __ldg(b0v + nb * 64 + cp);
            float f1 = Cs[(cp + 1) * 132 + m] + __ldg(b0v + nb * 64 + cp + 1);
            float g0 = Cs[(64 + cp) * 132 + m] + __ldg(b1v + nb * 64 + cp);
            float g1 = Cs[(65 + cp) * 132 + m] + __ldg(b1v + nb * 64 + cp + 1);
            float z0 = tanhf(f0) / (1.0f + __expf(-g0));
            float z1 = tanhf(f1) / (1.0f + __expf(-g1));
            uint32_t lp, hp = pack_hl(z0, z1, lp);
            size_t go = ((size_t)(b * TDIM + t0 + m)) * CHN + nb * 64 + cp;
            *(uint32_t*)(g_zhi + go) = hp;
            *(uint32_t*)(g_zlo + go) = lp;
        }
    } else {
        for (int i = tid; i < 128 * 64; i += 256) {
            int c1 = i >> 7, m = i & 127;
            size_t go = ((size_t)(b * CHN + nb * 64 + c1)) * TDIM + t0 + m;
            float vr = Cs[c1 * 132 + m]        + __ldg(b0v + nb * 64 + c1) + x[go];
            float vs = Cs[(64 + c1) * 132 + m] + __ldg(b1v + nb * 64 + c1);
            out[go]           = vr;
            out[SKIPOFF + go] = vs;
        }
    }
}

// ---------------------------------------------------------------------------
extern "C" void kernel_launch(void* const* d_in, const int* in_sizes, int n_in,
                              void* d_out, int out_size)
{
    const float* x   = (const float*)d_in[0];
    const float* wf  = (const float*)d_in[1];
    const float* bf  = (const float*)d_in[2];
    const float* wg  = (const float*)d_in[3];
    const float* bg  = (const float*)d_in[4];
    const float* wr  = (const float*)d_in[5];
    const float* br  = (const float*)d_in[6];
    const float* wsk = (const float*)d_in[7];
    const float* bsk = (const float*)d_in[8];
    float* out = (float*)d_out;

    cudaFuncSetAttribute(gemm_tc<1>, cudaFuncAttributeMaxDynamicSharedMemorySize, 81920);
    cudaFuncSetAttribute(gemm_tc<2>, cudaFuncAttributeMaxDynamicSharedMemorySize, 81920);

    pack_w_kernel<<<1536, 256>>>(wf, wg, wr, wsk);
    pack_x_kernel<<<dim3(64, 4, BATCH), 256>>>(x);
    dim3 grid(32, 4, BATCH);
    gemm_tc<1><<<grid, 256, 81920>>>(x, bf, bg, out);
    gemm_tc<2><<<grid, 256, 81920>>>(x, br, bsk, out);
}

// round 5
// speedup vs baseline: 3.9461x; 1.2801x over previous
#include <cuda_runtime.h>
#include <cuda_fp16.h>
#include <cstdint>
#include <math.h>

#define CHN 256
#define TDIM 4096
#define BATCH 16
#define SKIPOFF ((size_t)BATCH*CHN*TDIM)

// fp16 planes (device globals: allocation-free)
__device__ __half g_xhi[(size_t)BATCH*4104*CHN];
__device__ __half g_xlo[(size_t)BATCH*4104*CHN];
__device__ __half g_zhi[(size_t)BATCH*TDIM*CHN];
__device__ __half g_zlo[(size_t)BATCH*TDIM*CHN];
__device__ __half g_w1[4*128*512];
__device__ __half g_w2[4*128*256];

// stage: A-hi 10240 | A-lo 10240 | B 10240  (pitch 80 B per 32-K row)
#define STG 30720

// ---------------- helpers ----------------
__device__ __forceinline__ uint32_t smem_u32(const void* p) {
    uint32_t a; asm("{ .reg .u64 t; cvta.to.shared.u64 t, %1; cvt.u32.u64 %0, t; }" : "=r"(a) : "l"(p));
    return a;
}
__device__ __forceinline__ void cp16(uint32_t d, const void* s) {
    asm volatile("cp.async.cg.shared.global [%0], [%1], 16;" :: "r"(d), "l"(s));
}
__device__ __forceinline__ void ldmx4(uint32_t* r, uint32_t a) {
    asm volatile("ldmatrix.sync.aligned.m8n8.x4.shared.b16 {%0,%1,%2,%3}, [%4];"
        : "=r"(r[0]), "=r"(r[1]), "=r"(r[2]), "=r"(r[3]) : "r"(a));
}
__device__ __forceinline__ void mma_h(float* d, const uint32_t* a, const uint32_t* b) {
    asm volatile("mma.sync.aligned.m16n8k16.row.col.f32.f16.f16.f32 "
        "{%0,%1,%2,%3}, {%4,%5,%6,%7}, {%8,%9}, {%0,%1,%2,%3};"
        : "+f"(d[0]), "+f"(d[1]), "+f"(d[2]), "+f"(d[3])
        : "r"(a[0]), "r"(a[1]), "r"(a[2]), "r"(a[3]), "r"(b[0]), "r"(b[1]));
}
__device__ __forceinline__ uint32_t pack_hl(float v0, float v1, uint32_t& lopack) {
    __half h0 = __float2half_rn(v0), h1 = __float2half_rn(v1);
    __half l0 = __float2half_rn(v0 - __half2float(h0));
    __half l1 = __float2half_rn(v1 - __half2float(h1));
    lopack = ((uint32_t)__half_as_ushort(l1) << 16) | __half_as_ushort(l0);
    return ((uint32_t)__half_as_ushort(h1) << 16) | __half_as_ushort(h0);
}

// ---------------------------------------------------------------------------
// Weights: g_w1[nb][n'][k]: n'<64 filter ch nb*64+n', n'>=64 gate;
//   k<256 -> tap1 (pairs x[t]), k>=256 -> tap0 (pairs x[t-8]).
// g_w2[nb][n'][k]: n'<64 res, else skip.
// ---------------------------------------------------------------------------
__global__ void pack_w_kernel(const float* __restrict__ wf, const float* __restrict__ wg,
                              const float* __restrict__ wr, const float* __restrict__ wsk)
{
    int idx = blockIdx.x * blockDim.x + threadIdx.x;
    if (idx < 262144) {
        int nb = idx >> 16, np = (idx >> 9) & 127, k = idx & 511;
        int o = nb * 64 + (np & 63), c = k & 255;
        const float* w = (np < 64) ? wf : wg;
        g_w1[idx] = __float2half_rn(w[o * 512 + c * 2 + ((k < 256) ? 1 : 0)]);
    } else if (idx < 393216) {
        int j = idx - 262144;
        int nb = j >> 15, np = (j >> 8) & 127, k = j & 255;
        int o = nb * 64 + (np & 63);
        g_w2[j] = __float2half_rn((np < 64) ? wr[o * 256 + k] : wsk[o * 256 + k]);
    }
}

// ---------------------------------------------------------------------------
// x -> [b][r=t+8][256] hi/lo fp16 planes (rows 0-7 zero). grid(64,4,16).
// ---------------------------------------------------------------------------
__global__ void pack_x_kernel(const float* __restrict__ x)
{
    __shared__ float st[64][65];
    int tc = blockIdx.x, cc = blockIdx.y, b = blockIdx.z, tid = threadIdx.x;
    for (int i = tid; i < 64 * 16; i += 256) {
        int c = i >> 4, q = i & 15;
        float4 v = *(const float4*)(x + ((size_t)(b * CHN + cc * 64 + c)) * TDIM + tc * 64 + q * 4);
        st[q*4+0][c] = v.x; st[q*4+1][c] = v.y; st[q*4+2][c] = v.z; st[q*4+3][c] = v.w;
    }
    __syncthreads();
    for (int i = tid; i < 64 * 32; i += 256) {
        int r = i >> 5, cp = (i & 31) * 2;
        uint32_t lp, hp = pack_hl(st[r][cp], st[r][cp + 1], lp);
        size_t go = ((size_t)b * 4104 + tc * 64 + 8 + r) * CHN + cc * 64 + cp;
        *(uint32_t*)(g_xhi + go) = hp;
        *(uint32_t*)(g_xlo + go) = lp;
    }
    if (tc == 0)
        for (int i = tid; i < 8 * 32; i += 256) {
            int r = i >> 5, cp = (i & 31) * 2;
            size_t go = ((size_t)b * 4104 + r) * CHN + cc * 64 + cp;
            *(uint32_t*)(g_xhi + go) = 0;
            *(uint32_t*)(g_xlo + go) = 0;
        }
}

// ---------------------------------------------------------------------------
// GEMM: C[128 t][128 n] = A[t][K] * B[n][K]^T, 2-pass fp16 split (A hi/lo, B single).
// PHASE 1: A=x image, K=512, epilogue tanh*sigmoid -> z planes.
// PHASE 2: A=z planes, K=256, epilogue bias (+x for res) -> out.
// 8 warps (2m x 4n), warp tile 64x32, 2-stage cp.async, 2 CTAs/SM.
// ---------------------------------------------------------------------------
template<int PHASE>
__global__ void __launch_bounds__(256, 2) gemm_tc(
    const float* __restrict__ x, const float* __restrict__ b0v,
    const float* __restrict__ b1v, float* __restrict__ out)
{
    extern __shared__ unsigned char smraw[];
    const uint32_t sb = smem_u32(smraw);
    const int tid = threadIdx.x, lane = tid & 31, wid = tid >> 5;
    const int wm = wid & 1, wn = wid >> 1;
    const int tt = blockIdx.x, nb = blockIdx.y, b = blockIdx.z;
    const int t0 = tt * 128;
    const int NK  = (PHASE == 1) ? 16 : 8;
    const int KST = (PHASE == 1) ? 512 : 256;

    const __half* Ahi = (PHASE == 1) ? g_xhi + (size_t)b * 4104 * CHN
                                     : g_zhi + (size_t)b * TDIM * CHN;
    const __half* Alo = (PHASE == 1) ? g_xlo + (size_t)b * 4104 * CHN
                                     : g_zlo + (size_t)b * TDIM * CHN;
    const __half* Bw  = (PHASE == 1) ? g_w1 + nb * 128 * 512 : g_w2 + nb * 128 * 256;

    float acc[4][4][4];
    #pragma unroll
    for (int mi = 0; mi < 4; mi++)
        #pragma unroll
        for (int ni = 0; ni < 4; ni++)
            #pragma unroll
            for (int j = 0; j < 4; j++) acc[mi][ni][j] = 0.0f;

    auto load_stage = [&](int kc, int stg) {
        int koff = (PHASE == 1 && kc < 8) ? 8 : 0;
        int acol = (PHASE == 1) ? (kc & 7) * 32 : kc * 32;
        uint32_t sbase = sb + stg * STG;
        #pragma unroll
        for (int i = 0; i < 6; i++) {
            int idx = tid + i * 256;
            int r = (idx >> 2) & 127, seg = idx & 3;
            if (idx < 1024) {
                int pl = idx >> 9;
                const __half* asrc = (pl ? Alo : Ahi) + (size_t)(t0 + r + koff) * CHN + acol + seg * 8;
                cp16(sbase + pl * 10240 + r * 80 + seg * 16, asrc);
            } else {
                const __half* bsrc = Bw + (size_t)r * KST + kc * 32 + seg * 8;
                cp16(sbase + 20480 + r * 80 + seg * 16, bsrc);
            }
        }
        asm volatile("cp.async.commit_group;" ::: "memory");
    };

    load_stage(0, 0);
    load_stage(1, 1);

    for (int kc = 0; kc < NK; kc++) {
        if (kc < NK - 1) asm volatile("cp.async.wait_group 1;" ::: "memory");
        else             asm volatile("cp.async.wait_group 0;" ::: "memory");
        __syncthreads();

        const uint32_t abase = sb + (kc & 1) * STG;
        const uint32_t bbase = abase + 20480;
        #pragma unroll
        for (int ks = 0; ks < 2; ks++) {
            uint32_t ah[4][4], al[4][4], bf2[4][2];
            const int arow = lane & 15, acoll = ks * 16 + (lane >> 4) * 8;
            #pragma unroll
            for (int mi = 0; mi < 4; mi++) {
                uint32_t ad = abase + (wm * 64 + mi * 16 + arow) * 80 + acoll * 2;
                ldmx4(ah[mi], ad);
                ldmx4(al[mi], ad + 10240);
            }
            const int brow = (lane & 7) + ((lane >> 4) << 3);
            const int bcol = ks * 16 + ((lane >> 3) & 1) * 8;
            #pragma unroll
            for (int ni2 = 0; ni2 < 2; ni2++) {
                uint32_t t4[4];
                ldmx4(t4, bbase + (wn * 32 + ni2 * 16 + brow) * 80 + bcol * 2);
                bf2[ni2*2][0] = t4[0]; bf2[ni2*2][1] = t4[1];
                bf2[ni2*2+1][0] = t4[2]; bf2[ni2*2+1][1] = t4[3];
            }
            #pragma unroll
            for (int mi = 0; mi < 4; mi++)
                #pragma unroll
                for (int ni = 0; ni < 4; ni++) {
                    mma_h(acc[mi][ni], ah[mi], bf2[ni]);
                    mma_h(acc[mi][ni], al[mi], bf2[ni]);
                }
        }
        __syncthreads();
        if (kc + 2 < NK) load_stage(kc + 2, kc & 1);
    }
    __syncthreads();

    // ---- stage C through smem [128 n][132 m] ----
    float* Cs = (float*)smraw;
    {
        const int tr = lane >> 2, tc4 = (lane & 3) * 2;
        #pragma unroll
        for (int mi = 0; mi < 4; mi++)
            #pragma unroll
            for (int ni = 0; ni < 4; ni++) {
                int n0 = wn * 32 + ni * 8 + tc4;
                int m0 = wm * 64 + mi * 16 + tr;
                Cs[n0 * 132 + m0]           = acc[mi][ni][0];
                Cs[(n0 + 1) * 132 + m0]     = acc[mi][ni][1];
                Cs[n0 * 132 + m0 + 8]       = acc[mi][ni][2];
                Cs[(n0 + 1) * 132 + m0 + 8] = acc[mi][ni][3];
            }
    }
    __syncthreads();

    if (PHASE == 1) {
        for (int i = tid; i < 128 * 32; i += 256) {
            int m = i >> 5, cp = (i & 31) * 2;
            float f0 = Cs[cp * 132 + m]        + __ldg(b0v + nb * 64 + cp);
            float f1 = Cs[(cp + 1) * 132 + m]  + __ldg(b0v + nb * 64 + cp + 1);
            float g0 = Cs[(64 + cp) * 132 + m] + __ldg(b1v + nb * 64 + cp);
            float g1 = Cs[(65 + cp) * 132 + m] + __ldg(b1v + nb * 64 + cp + 1);
            float z0 = tanhf(f0) / (1.0f + __expf(-g0));
            float z1 = tanhf(f1) / (1.0f + __expf(-g1));
            uint32_t lp, hp = pack_hl(z0, z1, lp);
            size_t go = ((size_t)(b * TDIM + t0 + m)) * CHN + nb * 64 + cp;
            *(uint32_t*)(g_zhi + go) = hp;
            *(uint32_t*)(g_zlo + go) = lp;
        }
    } else {
        for (int i = tid; i < 128 * 64; i += 256) {
            int c1 = i >> 7, m = i & 127;
            size_t go = ((size_t)(b * CHN + nb * 64 + c1)) * TDIM + t0 + m;
            float vr = Cs[c1 * 132 + m]        + __ldg(b0v + nb * 64 + c1) + x[go];
            float vs = Cs[(64 + c1) * 132 + m] + __ldg(b1v + nb * 64 + c1);
            out[go]           = vr;
            out[SKIPOFF + go] = vs;
        }
    }
}

// ---------------------------------------------------------------------------
extern "C" void kernel_launch(void* const* d_in, const int* in_sizes, int n_in,
                              void* d_out, int out_size)
{
    const float* x   = (const float*)d_in[0];
    const float* wf  = (const float*)d_in[1];
    const float* bf  = (const float*)d_in[2];
    const float* wg  = (const float*)d_in[3];
    const float* bg  = (const float*)d_in[4];
    const float* wr  = (const float*)d_in[5];
    const float* br  = (const float*)d_in[6];
    const float* wsk = (const float*)d_in[7];
    const float* bsk = (const float*)d_in[8];
    float* out = (float*)d_out;

    cudaFuncSetAttribute(gemm_tc<1>, cudaFuncAttributeMaxDynamicSharedMemorySize, 67584);
    cudaFuncSetAttribute(gemm_tc<2>, cudaFuncAttributeMaxDynamicSharedMemorySize, 67584);

    pack_w_kernel<<<1536, 256>>>(wf, wg, wr, wsk);
    pack_x_kernel<<<dim3(64, 4, BATCH), 256>>>(x);
    dim3 grid(32, 4, BATCH);
    gemm_tc<1><<<grid, 256, 67584>>>(x, bf, bg, out);
    gemm_tc<2><<<grid, 256, 67584>>>(x, br, bsk, out);
}

// round 6
// speedup vs baseline: 4.0726x; 1.0320x over previous
#include <cuda_runtime.h>
#include <cuda_fp16.h>
#include <cstdint>
#include <math.h>

#define CHN 256
#define TDIM 4096
#define BATCH 16
#define SKIPOFF ((size_t)BATCH*CHN*TDIM)

// fp16 planes (device globals: allocation-free)
__device__ __half g_xhi[(size_t)BATCH*4104*CHN];
__device__ __half g_xlo[(size_t)BATCH*4104*CHN];
__device__ __half g_zhi[(size_t)BATCH*TDIM*CHN];
__device__ __half g_zlo[(size_t)BATCH*TDIM*CHN];
__device__ __half g_w1[4*128*512];
__device__ __half g_w2[4*128*256];

// stage: A-hi 10240 | A-lo 10240 | B 10240  (pitch 80 B per 32-K row)
#define STG 30720
#define NSTG 3
#define SMEM_SZ (STG*NSTG)   // 92160; C staging (67584) reuses this region

// ---------------- helpers ----------------
__device__ __forceinline__ uint32_t smem_u32(const void* p) {
    uint32_t a; asm("{ .reg .u64 t; cvta.to.shared.u64 t, %1; cvt.u32.u64 %0, t; }" : "=r"(a) : "l"(p));
    return a;
}
__device__ __forceinline__ void cp16(uint32_t d, const void* s) {
    asm volatile("cp.async.cg.shared.global [%0], [%1], 16;" :: "r"(d), "l"(s));
}
__device__ __forceinline__ void ldmx4(uint32_t* r, uint32_t a) {
    asm volatile("ldmatrix.sync.aligned.m8n8.x4.shared.b16 {%0,%1,%2,%3}, [%4];"
        : "=r"(r[0]), "=r"(r[1]), "=r"(r[2]), "=r"(r[3]) : "r"(a));
}
__device__ __forceinline__ void mma_h(float* d, const uint32_t* a, const uint32_t* b) {
    asm volatile("mma.sync.aligned.m16n8k16.row.col.f32.f16.f16.f32 "
        "{%0,%1,%2,%3}, {%4,%5,%6,%7}, {%8,%9}, {%0,%1,%2,%3};"
        : "+f"(d[0]), "+f"(d[1]), "+f"(d[2]), "+f"(d[3])
        : "r"(a[0]), "r"(a[1]), "r"(a[2]), "r"(a[3]), "r"(b[0]), "r"(b[1]));
}
__device__ __forceinline__ uint32_t pack_hl(float v0, float v1, uint32_t& lopack) {
    __half h0 = __float2half_rn(v0), h1 = __float2half_rn(v1);
    __half l0 = __float2half_rn(v0 - __half2float(h0));
    __half l1 = __float2half_rn(v1 - __half2float(h1));
    lopack = ((uint32_t)__half_as_ushort(l1) << 16) | __half_as_ushort(l0);
    return ((uint32_t)__half_as_ushort(h1) << 16) | __half_as_ushort(h0);
}
// z = tanh(f)*sigmoid(g), via fast exp (|f|,|g| small; no overflow in practice)
__device__ __forceinline__ float gatedact(float f, float g) {
    float ef = __expf(2.0f * f);
    float tf = __fdividef(ef - 1.0f, ef + 1.0f);
    float sg = __fdividef(1.0f, 1.0f + __expf(-g));
    return tf * sg;
}

// ---------------------------------------------------------------------------
// Weights: g_w1[nb][n'][k]: n'<64 filter ch nb*64+n', n'>=64 gate;
//   k<256 -> tap1 (pairs x[t]), k>=256 -> tap0 (pairs x[t-8]).
// g_w2[nb][n'][k]: n'<64 res, else skip.
// ---------------------------------------------------------------------------
__global__ void pack_w_kernel(const float* __restrict__ wf, const float* __restrict__ wg,
                              const float* __restrict__ wr, const float* __restrict__ wsk)
{
    int idx = blockIdx.x * blockDim.x + threadIdx.x;
    if (idx < 262144) {
        int nb = idx >> 16, np = (idx >> 9) & 127, k = idx & 511;
        int o = nb * 64 + (np & 63), c = k & 255;
        const float* w = (np < 64) ? wf : wg;
        g_w1[idx] = __float2half_rn(w[o * 512 + c * 2 + ((k < 256) ? 1 : 0)]);
    } else if (idx < 393216) {
        int j = idx - 262144;
        int nb = j >> 15, np = (j >> 8) & 127, k = j & 255;
        int o = nb * 64 + (np & 63);
        g_w2[j] = __float2half_rn((np < 64) ? wr[o * 256 + k] : wsk[o * 256 + k]);
    }
}

// ---------------------------------------------------------------------------
// x -> [b][r=t+8][256] hi/lo fp16 planes (rows 0-7 zero). grid(64,4,16).
// ---------------------------------------------------------------------------
__global__ void pack_x_kernel(const float* __restrict__ x)
{
    __shared__ float st[64][65];
    int tc = blockIdx.x, cc = blockIdx.y, b = blockIdx.z, tid = threadIdx.x;
    for (int i = tid; i < 64 * 16; i += 256) {
        int c = i >> 4, q = i & 15;
        float4 v = *(const float4*)(x + ((size_t)(b * CHN + cc * 64 + c)) * TDIM + tc * 64 + q * 4);
        st[q*4+0][c] = v.x; st[q*4+1][c] = v.y; st[q*4+2][c] = v.z; st[q*4+3][c] = v.w;
    }
    __syncthreads();
    for (int i = tid; i < 64 * 32; i += 256) {
        int r = i >> 5, cp = (i & 31) * 2;
        uint32_t lp, hp = pack_hl(st[r][cp], st[r][cp + 1], lp);
        size_t go = ((size_t)b * 4104 + tc * 64 + 8 + r) * CHN + cc * 64 + cp;
        *(uint32_t*)(g_xhi + go) = hp;
        *(uint32_t*)(g_xlo + go) = lp;
    }
    if (tc == 0)
        for (int i = tid; i < 8 * 32; i += 256) {
            int r = i >> 5, cp = (i & 31) * 2;
            size_t go = ((size_t)b * 4104 + r) * CHN + cc * 64 + cp;
            *(uint32_t*)(g_xhi + go) = 0;
            *(uint32_t*)(g_xlo + go) = 0;
        }
}

// ---------------------------------------------------------------------------
// GEMM: C[128 t][128 n] = A[t][K] * B[n][K]^T, 2-pass fp16 split (A hi/lo, B single).
// PHASE 1: A=x image, K=512, epilogue tanh*sigmoid -> z planes.
// PHASE 2: A=z planes, K=256, epilogue bias (+x for res) -> out.
// 8 warps (2m x 4n), warp tile 64x32, 3-stage cp.async ring, 1 barrier/iter.
// ---------------------------------------------------------------------------
template<int PHASE>
__global__ void __launch_bounds__(256, 2) gemm_tc(
    const float* __restrict__ x, const float* __restrict__ b0v,
    const float* __restrict__ b1v, float* __restrict__ out)
{
    extern __shared__ unsigned char smraw[];
    const uint32_t sb = smem_u32(smraw);
    const int tid = threadIdx.x, lane = tid & 31, wid = tid >> 5;
    const int wm = wid & 1, wn = wid >> 1;
    const int tt = blockIdx.x, nb = blockIdx.y, b = blockIdx.z;
    const int t0 = tt * 128;
    const int NK  = (PHASE == 1) ? 16 : 8;
    const int KST = (PHASE == 1) ? 512 : 256;

    const __half* Ahi = (PHASE == 1) ? g_xhi + (size_t)b * 4104 * CHN
                                     : g_zhi + (size_t)b * TDIM * CHN;
    const __half* Alo = (PHASE == 1) ? g_xlo + (size_t)b * 4104 * CHN
                                     : g_zlo + (size_t)b * TDIM * CHN;
    const __half* Bw  = (PHASE == 1) ? g_w1 + nb * 128 * 512 : g_w2 + nb * 128 * 256;

    float acc[4][4][4];
    #pragma unroll
    for (int mi = 0; mi < 4; mi++)
        #pragma unroll
        for (int ni = 0; ni < 4; ni++)
            #pragma unroll
            for (int j = 0; j < 4; j++) acc[mi][ni][j] = 0.0f;

    // per-thread cp.async source/dest decomposition (6 chunks of 16B)
    auto load_stage = [&](int kc, int stg) {
        int koff = (PHASE == 1 && kc < 8) ? 8 : 0;
        int acol = (PHASE == 1) ? (kc & 7) * 32 : kc * 32;
        uint32_t sbase = sb + stg * STG;
        #pragma unroll
        for (int i = 0; i < 6; i++) {
            int idx = tid + i * 256;
            int r = (idx >> 2) & 127, seg = idx & 3;
            if (idx < 1024) {
                int pl = idx >> 9;
                const __half* asrc = (pl ? Alo : Ahi) + (size_t)(t0 + r + koff) * CHN + acol + seg * 8;
                cp16(sbase + pl * 10240 + r * 80 + seg * 16, asrc);
            } else {
                const __half* bsrc = Bw + (size_t)r * KST + kc * 32 + seg * 8;
                cp16(sbase + 20480 + r * 80 + seg * 16, bsrc);
            }
        }
        asm volatile("cp.async.commit_group;" ::: "memory");
    };

    load_stage(0, 0);
    load_stage(1, 1);

    int stg = 0;                       // stage index = kc % 3
    for (int kc = 0; kc < NK; kc++) {
        if (kc < NK - 1) asm volatile("cp.async.wait_group 1;" ::: "memory");
        else             asm volatile("cp.async.wait_group 0;" ::: "memory");
        __syncthreads();               // stage kc visible; prior iter's reads done

        // prefetch stage kc+2 into the slot freed by iter kc-1 (safe post-barrier)
        if (kc + 2 < NK) {
            int nstg = stg + 2; if (nstg >= NSTG) nstg -= NSTG;
            load_stage(kc + 2, nstg);
        }

        const uint32_t abase = sb + stg * STG;
        const uint32_t bbase = abase + 20480;
        #pragma unroll
        for (int ks = 0; ks < 2; ks++) {
            uint32_t ah[4][4], al[4][4], bf2[4][2];
            const int arow = lane & 15, acoll = ks * 16 + (lane >> 4) * 8;
            const int brow = (lane & 7) + ((lane >> 4) << 3);
            const int bcol = ks * 16 + ((lane >> 3) & 1) * 8;
            #pragma unroll
            for (int ni2 = 0; ni2 < 2; ni2++) {
                uint32_t t4[4];
                ldmx4(t4, bbase + (wn * 32 + ni2 * 16 + brow) * 80 + bcol * 2);
                bf2[ni2*2][0] = t4[0]; bf2[ni2*2][1] = t4[1];
                bf2[ni2*2+1][0] = t4[2]; bf2[ni2*2+1][1] = t4[3];
            }
            #pragma unroll
            for (int mi = 0; mi < 4; mi++) {
                uint32_t ad = abase + (wm * 64 + mi * 16 + arow) * 80 + acoll * 2;
                ldmx4(ah[mi], ad);
                ldmx4(al[mi], ad + 10240);
            }
            #pragma unroll
            for (int mi = 0; mi < 4; mi++)
                #pragma unroll
                for (int ni = 0; ni < 4; ni++) {
                    mma_h(acc[mi][ni], ah[mi], bf2[ni]);
                    mma_h(acc[mi][ni], al[mi], bf2[ni]);
                }
        }
        stg++; if (stg >= NSTG) stg = 0;
    }
    __syncthreads();

    // ---- stage C through smem [128 n][132 m] ----
    float* Cs = (float*)smraw;
    {
        const int tr = lane >> 2, tc4 = (lane & 3) * 2;
        #pragma unroll
        for (int mi = 0; mi < 4; mi++)
            #pragma unroll
            for (int ni = 0; ni < 4; ni++) {
                int n0 = wn * 32 + ni * 8 + tc4;
                int m0 = wm * 64 + mi * 16 + tr;
                Cs[n0 * 132 + m0]           = acc[mi][ni][0];
                Cs[(n0 + 1) * 132 + m0]     = acc[mi][ni][1];
                Cs[n0 * 132 + m0 + 8]       = acc[mi][ni][2];
                Cs[(n0 + 1) * 132 + m0 + 8] = acc[mi][ni][3];
            }
    }
    __syncthreads();

    if (PHASE == 1) {
        for (int i = tid; i < 128 * 32; i += 256) {
            int m = i >> 5, cp = (i & 31) * 2;
            float f0 = Cs[cp * 132 + m]        + __ldg(b0v + nb * 64 + cp);
            float f1 = Cs[(cp + 1) * 132 + m]  + __ldg(b0v + nb * 64 + cp + 1);
            float g0 = Cs[(64 + cp) * 132 + m] + __ldg(b1v + nb * 64 + cp);
            float g1 = Cs[(65 + cp) * 132 + m] + __ldg(b1v + nb * 64 + cp + 1);
            uint32_t lp, hp = pack_hl(gatedact(f0, g0), gatedact(f1, g1), lp);
            size_t go = ((size_t)(b * TDIM + t0 + m)) * CHN + nb * 64 + cp;
            *(uint32_t*)(g_zhi + go) = hp;
            *(uint32_t*)(g_zlo + go) = lp;
        }
    } else {
        for (int i = tid; i < 128 * 64; i += 256) {
            int c1 = i >> 7, m = i & 127;
            size_t go = ((size_t)(b * CHN + nb * 64 + c1)) * TDIM + t0 + m;
            float vr = Cs[c1 * 132 + m]        + __ldg(b0v + nb * 64 + c1) + x[go];
            float vs = Cs[(64 + c1) * 132 + m] + __ldg(b1v + nb * 64 + c1);
            out[go]           = vr;
            out[SKIPOFF + go] = vs;
        }
    }
}

// ---------------------------------------------------------------------------
extern "C" void kernel_launch(void* const* d_in, const int* in_sizes, int n_in,
                              void* d_out, int out_size)
{
    const float* x   = (const float*)d_in[0];
    const float* wf  = (const float*)d_in[1];
    const float* bf  = (const float*)d_in[2];
    const float* wg  = (const float*)d_in[3];
    const float* bg  = (const float*)d_in[4];
    const float* wr  = (const float*)d_in[5];
    const float* br  = (const float*)d_in[6];
    const float* wsk = (const float*)d_in[7];
    const float* bsk = (const float*)d_in[8];
    float* out = (float*)d_out;

    cudaFuncSetAttribute(gemm_tc<1>, cudaFuncAttributeMaxDynamicSharedMemorySize, SMEM_SZ);
    cudaFuncSetAttribute(gemm_tc<2>, cudaFuncAttributeMaxDynamicSharedMemorySize, SMEM_SZ);

    pack_w_kernel<<<1536, 256>>>(wf, wg, wr, wsk);
    pack_x_kernel<<<dim3(64, 4, BATCH), 256>>>(x);
    dim3 grid(32, 4, BATCH);
    gemm_tc<1><<<grid, 256, SMEM_SZ>>>(x, bf, bg, out);
    gemm_tc<2><<<grid, 256, SMEM_SZ>>>(x, br, bsk, out);
}

// round 7
// speedup vs baseline: 4.0774x; 1.0012x over previous
#include <cuda_runtime.h>
#include <cuda_fp16.h>
#include <cstdint>
#include <math.h>

#define CHN 256
#define TDIM 4096
#define BATCH 16
#define SKIPOFF ((size_t)BATCH*CHN*TDIM)

// fp16 planes (device globals: allocation-free)
__device__ __half g_xhi[(size_t)BATCH*4104*CHN];
__device__ __half g_xlo[(size_t)BATCH*4104*CHN];
__device__ __half g_zhi[(size_t)BATCH*TDIM*CHN];
__device__ __half g_zlo[(size_t)BATCH*TDIM*CHN];
__device__ __half g_w1[4*128*512];
__device__ __half g_w2[4*128*256];

// stage: A-hi 10240 | A-lo 10240 | B 10240  (pitch 80 B per 32-K row)
#define STG 30720
#define NSTG 3
#define SMEM_SZ (STG*NSTG)   // 92160; C staging (67584) reuses this region

// ---------------- helpers ----------------
__device__ __forceinline__ uint32_t smem_u32(const void* p) {
    uint32_t a; asm("{ .reg .u64 t; cvta.to.shared.u64 t, %1; cvt.u32.u64 %0, t; }" : "=r"(a) : "l"(p));
    return a;
}
__device__ __forceinline__ void cp16(uint32_t d, const void* s) {
    asm volatile("cp.async.cg.shared.global [%0], [%1], 16;" :: "r"(d), "l"(s));
}
__device__ __forceinline__ void ldmx4(uint32_t* r, uint32_t a) {
    asm volatile("ldmatrix.sync.aligned.m8n8.x4.shared.b16 {%0,%1,%2,%3}, [%4];"
        : "=r"(r[0]), "=r"(r[1]), "=r"(r[2]), "=r"(r[3]) : "r"(a));
}
__device__ __forceinline__ void mma_h(float* d, const uint32_t* a, const uint32_t* b) {
    asm volatile("mma.sync.aligned.m16n8k16.row.col.f32.f16.f16.f32 "
        "{%0,%1,%2,%3}, {%4,%5,%6,%7}, {%8,%9}, {%0,%1,%2,%3};"
        : "+f"(d[0]), "+f"(d[1]), "+f"(d[2]), "+f"(d[3])
        : "r"(a[0]), "r"(a[1]), "r"(a[2]), "r"(a[3]), "r"(b[0]), "r"(b[1]));
}
__device__ __forceinline__ uint32_t pack_hl(float v0, float v1, uint32_t& lopack) {
    __half h0 = __float2half_rn(v0), h1 = __float2half_rn(v1);
    __half l0 = __float2half_rn(v0 - __half2float(h0));
    __half l1 = __float2half_rn(v1 - __half2float(h1));
    lopack = ((uint32_t)__half_as_ushort(l1) << 16) | __half_as_ushort(l0);
    return ((uint32_t)__half_as_ushort(h1) << 16) | __half_as_ushort(h0);
}
__device__ __forceinline__ float gatedact(float f, float g) {
    float ef = __expf(2.0f * f);
    float tf = __fdividef(ef - 1.0f, ef + 1.0f);
    float sg = __fdividef(1.0f, 1.0f + __expf(-g));
    return tf * sg;
}

// ---------------------------------------------------------------------------
// Weights: g_w1[nb][n'][k]: n'<64 filter ch nb*64+n', n'>=64 gate;
//   k<256 -> tap1 (pairs x[t]), k>=256 -> tap0 (pairs x[t-8]).
// g_w2[nb][n'][k]: n'<64 res, else skip.
// ---------------------------------------------------------------------------
__global__ void pack_w_kernel(const float* __restrict__ wf, const float* __restrict__ wg,
                              const float* __restrict__ wr, const float* __restrict__ wsk)
{
    int idx = blockIdx.x * blockDim.x + threadIdx.x;
    if (idx < 262144) {
        int nb = idx >> 16, np = (idx >> 9) & 127, k = idx & 511;
        int o = nb * 64 + (np & 63), c = k & 255;
        const float* w = (np < 64) ? wf : wg;
        g_w1[idx] = __float2half_rn(w[o * 512 + c * 2 + ((k < 256) ? 1 : 0)]);
    } else if (idx < 393216) {
        int j = idx - 262144;
        int nb = j >> 15, np = (j >> 8) & 127, k = j & 255;
        int o = nb * 64 + (np & 63);
        g_w2[j] = __float2half_rn((np < 64) ? wr[o * 256 + k] : wsk[o * 256 + k]);
    }
}

// ---------------------------------------------------------------------------
// x -> [b][r=t+8][256] hi/lo fp16 planes (rows 0-7 zero). grid(64,4,16).
// ---------------------------------------------------------------------------
__global__ void pack_x_kernel(const float* __restrict__ x)
{
    __shared__ float st[64][65];
    int tc = blockIdx.x, cc = blockIdx.y, b = blockIdx.z, tid = threadIdx.x;
    for (int i = tid; i < 64 * 16; i += 256) {
        int c = i >> 4, q = i & 15;
        float4 v = *(const float4*)(x + ((size_t)(b * CHN + cc * 64 + c)) * TDIM + tc * 64 + q * 4);
        st[q*4+0][c] = v.x; st[q*4+1][c] = v.y; st[q*4+2][c] = v.z; st[q*4+3][c] = v.w;
    }
    __syncthreads();
    for (int i = tid; i < 64 * 32; i += 256) {
        int r = i >> 5, cp = (i & 31) * 2;
        uint32_t lp, hp = pack_hl(st[r][cp], st[r][cp + 1], lp);
        size_t go = ((size_t)b * 4104 + tc * 64 + 8 + r) * CHN + cc * 64 + cp;
        *(uint32_t*)(g_xhi + go) = hp;
        *(uint32_t*)(g_xlo + go) = lp;
    }
    if (tc == 0)
        for (int i = tid; i < 8 * 32; i += 256) {
            int r = i >> 5, cp = (i & 31) * 2;
            size_t go = ((size_t)b * 4104 + r) * CHN + cc * 64 + cp;
            *(uint32_t*)(g_xhi + go) = 0;
            *(uint32_t*)(g_xlo + go) = 0;
        }
}

// ---------------------------------------------------------------------------
// GEMM: C[128 t][128 n] = A[t][K] * B[n][K]^T, 2-pass fp16 split (A hi/lo, B single).
// PHASE 1: A=x image, K=512, epilogue tanh*sigmoid -> z planes.
// PHASE 2: A=z planes, K=256, epilogue bias (+x for res) -> out.
// 8 warps (2m x 4n), warp tile 64x32, 3-stage ring, hi-sweep/lo-sweep MMA order.
// ---------------------------------------------------------------------------
template<int PHASE>
__global__ void __launch_bounds__(256, 2) gemm_tc(
    const float* __restrict__ x, const float* __restrict__ b0v,
    const float* __restrict__ b1v, float* __restrict__ out)
{
    extern __shared__ unsigned char smraw[];
    const uint32_t sb = smem_u32(smraw);
    const int tid = threadIdx.x, lane = tid & 31, wid = tid >> 5;
    const int wm = wid & 1, wn = wid >> 1;
    const int tt = blockIdx.x, nb = blockIdx.y, b = blockIdx.z;
    const int t0 = tt * 128;
    const int NK  = (PHASE == 1) ? 16 : 8;
    const int KST = (PHASE == 1) ? 512 : 256;

    const __half* Ahi = (PHASE == 1) ? g_xhi + (size_t)b * 4104 * CHN
                                     : g_zhi + (size_t)b * TDIM * CHN;
    const __half* Alo = (PHASE == 1) ? g_xlo + (size_t)b * 4104 * CHN
                                     : g_zlo + (size_t)b * TDIM * CHN;
    const __half* Bw  = (PHASE == 1) ? g_w1 + nb * 128 * 512 : g_w2 + nb * 128 * 256;

    float acc[4][4][4];
    #pragma unroll
    for (int mi = 0; mi < 4; mi++)
        #pragma unroll
        for (int ni = 0; ni < 4; ni++)
            #pragma unroll
            for (int j = 0; j < 4; j++) acc[mi][ni][j] = 0.0f;

    auto load_stage = [&](int kc, int stg) {
        int koff = (PHASE == 1 && kc < 8) ? 8 : 0;
        int acol = (PHASE == 1) ? (kc & 7) * 32 : kc * 32;
        uint32_t sbase = sb + stg * STG;
        #pragma unroll
        for (int i = 0; i < 6; i++) {
            int idx = tid + i * 256;
            int r = (idx >> 2) & 127, seg = idx & 3;
            if (idx < 1024) {
                int pl = idx >> 9;
                const __half* asrc = (pl ? Alo : Ahi) + (size_t)(t0 + r + koff) * CHN + acol + seg * 8;
                cp16(sbase + pl * 10240 + r * 80 + seg * 16, asrc);
            } else {
                const __half* bsrc = Bw + (size_t)r * KST + kc * 32 + seg * 8;
                cp16(sbase + 20480 + r * 80 + seg * 16, bsrc);
            }
        }
        asm volatile("cp.async.commit_group;" ::: "memory");
    };

    load_stage(0, 0);
    load_stage(1, 1);

    int stg = 0;                       // stage index = kc % 3
    for (int kc = 0; kc < NK; kc++) {
        if (kc < NK - 1) asm volatile("cp.async.wait_group 1;" ::: "memory");
        else             asm volatile("cp.async.wait_group 0;" ::: "memory");
        __syncthreads();

        if (kc + 2 < NK) {
            int nstg = stg + 2; if (nstg >= NSTG) nstg -= NSTG;
            load_stage(kc + 2, nstg);
        }

        const uint32_t abase = sb + stg * STG;
        const uint32_t bbase = abase + 20480;
        #pragma unroll
        for (int ks = 0; ks < 2; ks++) {
            uint32_t ah[4][4], al[4][4], bf2[4][2];
            const int arow = lane & 15, acoll = ks * 16 + (lane >> 4) * 8;
            const int brow = (lane & 7) + ((lane >> 4) << 3);
            const int bcol = ks * 16 + ((lane >> 3) & 1) * 8;
            #pragma unroll
            for (int ni2 = 0; ni2 < 2; ni2++) {
                uint32_t t4[4];
                ldmx4(t4, bbase + (wn * 32 + ni2 * 16 + brow) * 80 + bcol * 2);
                bf2[ni2*2][0] = t4[0]; bf2[ni2*2][1] = t4[1];
                bf2[ni2*2+1][0] = t4[2]; bf2[ni2*2+1][1] = t4[3];
            }
            #pragma unroll
            for (int mi = 0; mi < 4; mi++) {
                uint32_t ad = abase + (wm * 64 + mi * 16 + arow) * 80 + acoll * 2;
                ldmx4(ah[mi], ad);
                ldmx4(al[mi], ad + 10240);
            }
            // hi sweep: 16 independent accumulators (reuse distance 16)
            #pragma unroll
            for (int mi = 0; mi < 4; mi++)
                #pragma unroll
                for (int ni = 0; ni < 4; ni++)
                    mma_h(acc[mi][ni], ah[mi], bf2[ni]);
            // lo sweep
            #pragma unroll
            for (int mi = 0; mi < 4; mi++)
                #pragma unroll
                for (int ni = 0; ni < 4; ni++)
                    mma_h(acc[mi][ni], al[mi], bf2[ni]);
        }
        stg++; if (stg >= NSTG) stg = 0;
    }
    __syncthreads();

    // ---- stage C through smem [128 n][132 m] ----
    float* Cs = (float*)smraw;
    {
        const int tr = lane >> 2, tc4 = (lane & 3) * 2;
        #pragma unroll
        for (int mi = 0; mi < 4; mi++)
            #pragma unroll
            for (int ni = 0; ni < 4; ni++) {
                int n0 = wn * 32 + ni * 8 + tc4;
                int m0 = wm * 64 + mi * 16 + tr;
                Cs[n0 * 132 + m0]           = acc[mi][ni][0];
                Cs[(n0 + 1) * 132 + m0]     = acc[mi][ni][1];
                Cs[n0 * 132 + m0 + 8]       = acc[mi][ni][2];
                Cs[(n0 + 1) * 132 + m0 + 8] = acc[mi][ni][3];
            }
    }
    __syncthreads();

    if (PHASE == 1) {
        for (int i = tid; i < 128 * 32; i += 256) {
            int m = i >> 5, cp = (i & 31) * 2;
            float f0 = Cs[cp * 132 + m]        + __ldg(b0v + nb * 64 + cp);
            float f1 = Cs[(cp + 1) * 132 + m]  + __ldg(b0v + nb * 64 + cp + 1);
            float g0 = Cs[(64 + cp) * 132 + m] + __ldg(b1v + nb * 64 + cp);
            float g1 = Cs[(65 + cp) * 132 + m] + __ldg(b1v + nb * 64 + cp + 1);
            uint32_t lp, hp = pack_hl(gatedact(f0, g0), gatedact(f1, g1), lp);
            size_t go = ((size_t)(b * TDIM + t0 + m)) * CHN + nb * 64 + cp;
            *(uint32_t*)(g_zhi + go) = hp;
            *(uint32_t*)(g_zlo + go) = lp;
        }
    } else {
        for (int i = tid; i < 128 * 64; i += 256) {
            int c1 = i >> 7, m = i & 127;
            size_t go = ((size_t)(b * CHN + nb * 64 + c1)) * TDIM + t0 + m;
            float vr = Cs[c1 * 132 + m]        + __ldg(b0v + nb * 64 + c1) + x[go];
            float vs = Cs[(64 + c1) * 132 + m] + __ldg(b1v + nb * 64 + c1);
            out[go]           = vr;
            out[SKIPOFF + go] = vs;
        }
    }
}

// ---------------------------------------------------------------------------
extern "C" void kernel_launch(void* const* d_in, const int* in_sizes, int n_in,
                              void* d_out, int out_size)
{
    const float* x   = (const float*)d_in[0];
    const float* wf  = (const float*)d_in[1];
    const float* bf  = (const float*)d_in[2];
    const float* wg  = (const float*)d_in[3];
    const float* bg  = (const float*)d_in[4];
    const float* wr  = (const float*)d_in[5];
    const float* br  = (const float*)d_in[6];
    const float* wsk = (const float*)d_in[7];
    const float* bsk = (const float*)d_in[8];
    float* out = (float*)d_out;

    cudaFuncSetAttribute(gemm_tc<1>, cudaFuncAttributeMaxDynamicSharedMemorySize, SMEM_SZ);
    cudaFuncSetAttribute(gemm_tc<2>, cudaFuncAttributeMaxDynamicSharedMemorySize, SMEM_SZ);

    pack_w_kernel<<<1536, 256>>>(wf, wg, wr, wsk);
    pack_x_kernel<<<dim3(64, 4, BATCH), 256>>>(x);
    dim3 grid(32, 4, BATCH);
    gemm_tc<1><<<grid, 256, SMEM_SZ>>>(x, bf, bg, out);
    gemm_tc<2><<<grid, 256, SMEM_SZ>>>(x, br, bsk, out);
}

// round 8
// speedup vs baseline: 4.1655x; 1.0216x over previous
#include <cuda_runtime.h>
#include <cuda_fp16.h>
#include <cstdint>
#include <math.h>

#define CHN 256
#define TDIM 4096
#define BATCH 16
#define SKIPOFF ((size_t)BATCH*CHN*TDIM)

// single fp16 planes (device globals: allocation-free)
__device__ __half g_x[(size_t)BATCH*4104*CHN];
__device__ __half g_z[(size_t)BATCH*TDIM*CHN];
__device__ __half g_w1[4*128*512];
__device__ __half g_w2[4*128*256];

// stage: A 10240 | B 10240  (pitch 80 B per 32-K row)
#define STG 20480
#define NSTG 4
#define SMEM_SZ 81920   // 4 stages; C staging (67584) reuses this region

// ---------------- helpers ----------------
__device__ __forceinline__ uint32_t smem_u32(const void* p) {
    uint32_t a; asm("{ .reg .u64 t; cvta.to.shared.u64 t, %1; cvt.u32.u64 %0, t; }" : "=r"(a) : "l"(p));
    return a;
}
__device__ __forceinline__ void cp16(uint32_t d, const void* s) {
    asm volatile("cp.async.cg.shared.global [%0], [%1], 16;" :: "r"(d), "l"(s));
}
__device__ __forceinline__ void ldmx4(uint32_t* r, uint32_t a) {
    asm volatile("ldmatrix.sync.aligned.m8n8.x4.shared.b16 {%0,%1,%2,%3}, [%4];"
        : "=r"(r[0]), "=r"(r[1]), "=r"(r[2]), "=r"(r[3]) : "r"(a));
}
__device__ __forceinline__ void mma_h(float* d, const uint32_t* a, const uint32_t* b) {
    asm volatile("mma.sync.aligned.m16n8k16.row.col.f32.f16.f16.f32 "
        "{%0,%1,%2,%3}, {%4,%5,%6,%7}, {%8,%9}, {%0,%1,%2,%3};"
        : "+f"(d[0]), "+f"(d[1]), "+f"(d[2]), "+f"(d[3])
        : "r"(a[0]), "r"(a[1]), "r"(a[2]), "r"(a[3]), "r"(b[0]), "r"(b[1]));
}
__device__ __forceinline__ float gatedact(float f, float g) {
    float ef = __expf(2.0f * f);
    float tf = __fdividef(ef - 1.0f, ef + 1.0f);
    float sg = __fdividef(1.0f, 1.0f + __expf(-g));
    return tf * sg;
}

// ---------------------------------------------------------------------------
// Weights: g_w1[nb][n'][k]: n'<64 filter ch nb*64+n', n'>=64 gate;
//   k<256 -> tap1 (pairs x[t]), k>=256 -> tap0 (pairs x[t-8]).
// g_w2[nb][n'][k]: n'<64 res, else skip.
// ---------------------------------------------------------------------------
__global__ void pack_w_kernel(const float* __restrict__ wf, const float* __restrict__ wg,
                              const float* __restrict__ wr, const float* __restrict__ wsk)
{
    int idx = blockIdx.x * blockDim.x + threadIdx.x;
    if (idx < 262144) {
        int nb = idx >> 16, np = (idx >> 9) & 127, k = idx & 511;
        int o = nb * 64 + (np & 63), c = k & 255;
        const float* w = (np < 64) ? wf : wg;
        g_w1[idx] = __float2half_rn(w[o * 512 + c * 2 + ((k < 256) ? 1 : 0)]);
    } else if (idx < 393216) {
        int j = idx - 262144;
        int nb = j >> 15, np = (j >> 8) & 127, k = j & 255;
        int o = nb * 64 + (np & 63);
        g_w2[j] = __float2half_rn((np < 64) ? wr[o * 256 + k] : wsk[o * 256 + k]);
    }
}

// ---------------------------------------------------------------------------
// x -> [b][r=t+8][256] fp16 plane (rows 0-7 zero). grid(64,4,16).
// ---------------------------------------------------------------------------
__global__ void pack_x_kernel(const float* __restrict__ x)
{
    __shared__ float st[64][65];
    int tc = blockIdx.x, cc = blockIdx.y, b = blockIdx.z, tid = threadIdx.x;
    for (int i = tid; i < 64 * 16; i += 256) {
        int c = i >> 4, q = i & 15;
        float4 v = *(const float4*)(x + ((size_t)(b * CHN + cc * 64 + c)) * TDIM + tc * 64 + q * 4);
        st[q*4+0][c] = v.x; st[q*4+1][c] = v.y; st[q*4+2][c] = v.z; st[q*4+3][c] = v.w;
    }
    __syncthreads();
    for (int i = tid; i < 64 * 32; i += 256) {
        int r = i >> 5, cp = (i & 31) * 2;
        __half h0 = __float2half_rn(st[r][cp]), h1 = __float2half_rn(st[r][cp + 1]);
        size_t go = ((size_t)b * 4104 + tc * 64 + 8 + r) * CHN + cc * 64 + cp;
        *(uint32_t*)(g_x + go) = ((uint32_t)__half_as_ushort(h1) << 16) | __half_as_ushort(h0);
    }
    if (tc == 0)
        for (int i = tid; i < 8 * 32; i += 256) {
            int r = i >> 5, cp = (i & 31) * 2;
            *(uint32_t*)(g_x + ((size_t)b * 4104 + r) * CHN + cc * 64 + cp) = 0;
        }
}

// ---------------------------------------------------------------------------
// GEMM: C[128 t][128 n] = A[t][K] * B[n][K]^T, single-pass fp16.
// PHASE 1: A=x image, K=512, epilogue tanh*sigmoid -> z plane.
// PHASE 2: A=z plane, K=256, epilogue bias (+x for res) -> out.
// 8 warps (2m x 4n), warp tile 64x32, 4-stage ring, depth-3 prefetch.
// ---------------------------------------------------------------------------
template<int PHASE>
__global__ void __launch_bounds__(256, 2) gemm_tc(
    const float* __restrict__ x, const float* __restrict__ b0v,
    const float* __restrict__ b1v, float* __restrict__ out)
{
    extern __shared__ unsigned char smraw[];
    const uint32_t sb = smem_u32(smraw);
    const int tid = threadIdx.x, lane = tid & 31, wid = tid >> 5;
    const int wm = wid & 1, wn = wid >> 1;
    const int tt = blockIdx.x, nb = blockIdx.y, b = blockIdx.z;
    const int t0 = tt * 128;
    const int NK  = (PHASE == 1) ? 16 : 8;
    const int KST = (PHASE == 1) ? 512 : 256;

    const __half* Ap = (PHASE == 1) ? g_x + (size_t)b * 4104 * CHN
                                    : g_z + (size_t)b * TDIM * CHN;
    const __half* Bw = (PHASE == 1) ? g_w1 + nb * 128 * 512 : g_w2 + nb * 128 * 256;

    float acc[4][4][4];
    #pragma unroll
    for (int mi = 0; mi < 4; mi++)
        #pragma unroll
        for (int ni = 0; ni < 4; ni++)
            #pragma unroll
            for (int j = 0; j < 4; j++) acc[mi][ni][j] = 0.0f;

    auto load_stage = [&](int kc, int stg) {
        int koff = (PHASE == 1 && kc < 8) ? 8 : 0;
        int acol = (PHASE == 1) ? (kc & 7) * 32 : kc * 32;
        uint32_t sbase = sb + stg * STG;
        #pragma unroll
        for (int i = 0; i < 4; i++) {
            int idx = tid + i * 256;
            int r = (idx >> 2) & 127, seg = idx & 3;
            if (idx < 512) {
                const __half* asrc = Ap + (size_t)(t0 + r + koff) * CHN + acol + seg * 8;
                cp16(sbase + r * 80 + seg * 16, asrc);
            } else {
                const __half* bsrc = Bw + (size_t)r * KST + kc * 32 + seg * 8;
                cp16(sbase + 10240 + r * 80 + seg * 16, bsrc);
            }
        }
        asm volatile("cp.async.commit_group;" ::: "memory");
    };

    load_stage(0, 0);
    load_stage(1, 1);
    load_stage(2, 2);

    int stg = 0;
    for (int kc = 0; kc < NK; kc++) {
        int rem = NK - 1 - kc;
        if (rem >= 2)      asm volatile("cp.async.wait_group 2;" ::: "memory");
        else if (rem == 1) asm volatile("cp.async.wait_group 1;" ::: "memory");
        else               asm volatile("cp.async.wait_group 0;" ::: "memory");
        __syncthreads();

        if (kc + 3 < NK) {
            int nstg = stg + 3; if (nstg >= NSTG) nstg -= NSTG;
            load_stage(kc + 3, nstg);
        }

        const uint32_t abase = sb + stg * STG;
        const uint32_t bbase = abase + 10240;
        #pragma unroll
        for (int ks = 0; ks < 2; ks++) {
            uint32_t ah[4][4], bf2[4][2];
            const int arow = lane & 15, acoll = ks * 16 + (lane >> 4) * 8;
            const int brow = (lane & 7) + ((lane >> 4) << 3);
            const int bcol = ks * 16 + ((lane >> 3) & 1) * 8;
            #pragma unroll
            for (int ni2 = 0; ni2 < 2; ni2++) {
                uint32_t t4[4];
                ldmx4(t4, bbase + (wn * 32 + ni2 * 16 + brow) * 80 + bcol * 2);
                bf2[ni2*2][0] = t4[0]; bf2[ni2*2][1] = t4[1];
                bf2[ni2*2+1][0] = t4[2]; bf2[ni2*2+1][1] = t4[3];
            }
            #pragma unroll
            for (int mi = 0; mi < 4; mi++)
                ldmx4(ah[mi], abase + (wm * 64 + mi * 16 + arow) * 80 + acoll * 2);
            #pragma unroll
            for (int mi = 0; mi < 4; mi++)
                #pragma unroll
                for (int ni = 0; ni < 4; ni++)
                    mma_h(acc[mi][ni], ah[mi], bf2[ni]);
        }
        stg++; if (stg >= NSTG) stg = 0;
    }
    __syncthreads();

    // ---- stage C through smem [128 n][132 m] ----
    float* Cs = (float*)smraw;
    {
        const int tr = lane >> 2, tc4 = (lane & 3) * 2;
        #pragma unroll
        for (int mi = 0; mi < 4; mi++)
            #pragma unroll
            for (int ni = 0; ni < 4; ni++) {
                int n0 = wn * 32 + ni * 8 + tc4;
                int m0 = wm * 64 + mi * 16 + tr;
                Cs[n0 * 132 + m0]           = acc[mi][ni][0];
                Cs[(n0 + 1) * 132 + m0]     = acc[mi][ni][1];
                Cs[n0 * 132 + m0 + 8]       = acc[mi][ni][2];
                Cs[(n0 + 1) * 132 + m0 + 8] = acc[mi][ni][3];
            }
    }
    __syncthreads();

    if (PHASE == 1) {
        for (int i = tid; i < 128 * 32; i += 256) {
            int m = i >> 5, cp = (i & 31) * 2;
            float f0 = Cs[cp * 132 + m]        + __ldg(b0v + nb * 64 + cp);
            float f1 = Cs[(cp + 1) * 132 + m]  + __ldg(b0v + nb * 64 + cp + 1);
            float g0 = Cs[(64 + cp) * 132 + m] + __ldg(b1v + nb * 64 + cp);
            float g1 = Cs[(65 + cp) * 132 + m] + __ldg(b1v + nb * 64 + cp + 1);
            __half h0 = __float2half_rn(gatedact(f0, g0));
            __half h1 = __float2half_rn(gatedact(f1, g1));
            size_t go = ((size_t)(b * TDIM + t0 + m)) * CHN + nb * 64 + cp;
            *(uint32_t*)(g_z + go) = ((uint32_t)__half_as_ushort(h1) << 16) | __half_as_ushort(h0);
        }
    } else {
        for (int i = tid; i < 128 * 32; i += 256) {
            int c1 = i >> 5, mp = (i & 31) * 4;
            size_t go = ((size_t)(b * CHN + nb * 64 + ((c1 < 64) ? c1 : c1 - 64))) * TDIM + t0 + mp;
            if (c1 < 64) {
                float bias = __ldg(b0v + nb * 64 + c1);
                float4 xv = *(const float4*)(x + go);
                float4 v = make_float4(Cs[c1*132+mp]   + bias + xv.x,
                                       Cs[c1*132+mp+1] + bias + xv.y,
                                       Cs[c1*132+mp+2] + bias + xv.z,
                                       Cs[c1*132+mp+3] + bias + xv.w);
                *(float4*)(out + go) = v;
            } else {
                float bias = __ldg(b1v + nb * 64 + (c1 - 64));
                float4 v = make_float4(Cs[c1*132+mp]   + bias,
                                       Cs[c1*132+mp+1] + bias,
                                       Cs[c1*132+mp+2] + bias,
                                       Cs[c1*132+mp+3] + bias);
                *(float4*)(out + SKIPOFF + go) = v;
            }
        }
    }
}

// ---------------------------------------------------------------------------
extern "C" void kernel_launch(void* const* d_in, const int* in_sizes, int n_in,
                              void* d_out, int out_size)
{
    const float* x   = (const float*)d_in[0];
    const float* wf  = (const float*)d_in[1];
    const float* bf  = (const float*)d_in[2];
    const float* wg  = (const float*)d_in[3];
    const float* bg  = (const float*)d_in[4];
    const float* wr  = (const float*)d_in[5];
    const float* br  = (const float*)d_in[6];
    const float* wsk = (const float*)d_in[7];
    const float* bsk = (const float*)d_in[8];
    float* out = (float*)d_out;

    cudaFuncSetAttribute(gemm_tc<1>, cudaFuncAttributeMaxDynamicSharedMemorySize, SMEM_SZ);
    cudaFuncSetAttribute(gemm_tc<2>, cudaFuncAttributeMaxDynamicSharedMemorySize, SMEM_SZ);

    pack_w_kernel<<<1536, 256>>>(wf, wg, wr, wsk);
    pack_x_kernel<<<dim3(64, 4, BATCH), 256>>>(x);
    dim3 grid(32, 4, BATCH);
    gemm_tc<1><<<grid, 256, SMEM_SZ>>>(x, bf, bg, out);
    gemm_tc<2><<<grid, 256, SMEM_SZ>>>(x, br, bsk, out);
}

// round 9
// speedup vs baseline: 6.3185x; 1.5169x over previous
#include <cuda_runtime.h>
#include <cuda_fp16.h>
#include <cstdint>
#include <math.h>

#define CHN 256
#define TDIM 4096
#define BATCH 16
#define SKIPOFF ((size_t)BATCH*CHN*TDIM)

// single fp16 planes (device globals: allocation-free)
__device__ __half g_x[(size_t)BATCH*4104*CHN];
__device__ __half g_z[(size_t)BATCH*TDIM*CHN];
__device__ __half g_w1[4*128*512];
__device__ __half g_w2[4*128*256];

// stage: A 64 rows x 80B | B 128 rows x 80B
#define ASTG 5120
#define STG  15360
#define NSTG 4
#define SMEM_SZ 61440   // 4 stages; C staging (128*68*4=34816) reuses region

// ---------------- helpers ----------------
__device__ __forceinline__ uint32_t smem_u32(const void* p) {
    uint32_t a; asm("{ .reg .u64 t; cvta.to.shared.u64 t, %1; cvt.u32.u64 %0, t; }" : "=r"(a) : "l"(p));
    return a;
}
__device__ __forceinline__ void cp16(uint32_t d, const void* s) {
    asm volatile("cp.async.cg.shared.global [%0], [%1], 16;" :: "r"(d), "l"(s));
}
__device__ __forceinline__ void ldmx4(uint32_t* r, uint32_t a) {
    asm volatile("ldmatrix.sync.aligned.m8n8.x4.shared.b16 {%0,%1,%2,%3}, [%4];"
        : "=r"(r[0]), "=r"(r[1]), "=r"(r[2]), "=r"(r[3]) : "r"(a));
}
__device__ __forceinline__ void mma_h(float* d, const uint32_t* a, const uint32_t* b) {
    asm volatile("mma.sync.aligned.m16n8k16.row.col.f32.f16.f16.f32 "
        "{%0,%1,%2,%3}, {%4,%5,%6,%7}, {%8,%9}, {%0,%1,%2,%3};"
        : "+f"(d[0]), "+f"(d[1]), "+f"(d[2]), "+f"(d[3])
        : "r"(a[0]), "r"(a[1]), "r"(a[2]), "r"(a[3]), "r"(b[0]), "r"(b[1]));
}
__device__ __forceinline__ float gatedact(float f, float g) {
    float ef = __expf(2.0f * f);
    float tf = __fdividef(ef - 1.0f, ef + 1.0f);
    float sg = __fdividef(1.0f, 1.0f + __expf(-g));
    return tf * sg;
}

// ---------------------------------------------------------------------------
// Weights: g_w1[nb][n'][k]: n'<64 filter ch nb*64+n', n'>=64 gate;
//   k<256 -> tap1 (pairs x[t]), k>=256 -> tap0 (pairs x[t-8]).
// g_w2[nb][n'][k]: n'<64 res, else skip.
// ---------------------------------------------------------------------------
__global__ void pack_w_kernel(const float* __restrict__ wf, const float* __restrict__ wg,
                              const float* __restrict__ wr, const float* __restrict__ wsk)
{
    int idx = blockIdx.x * blockDim.x + threadIdx.x;
    if (idx < 262144) {
        int nb = idx >> 16, np = (idx >> 9) & 127, k = idx & 511;
        int o = nb * 64 + (np & 63), c = k & 255;
        const float* w = (np < 64) ? wf : wg;
        g_w1[idx] = __float2half_rn(w[o * 512 + c * 2 + ((k < 256) ? 1 : 0)]);
    } else if (idx < 393216) {
        int j = idx - 262144;
        int nb = j >> 15, np = (j >> 8) & 127, k = j & 255;
        int o = nb * 64 + (np & 63);
        g_w2[j] = __float2half_rn((np < 64) ? wr[o * 256 + k] : wsk[o * 256 + k]);
    }
}

// ---------------------------------------------------------------------------
// x -> [b][r=t+8][256] fp16 plane (rows 0-7 zero). grid(64,4,16).
// ---------------------------------------------------------------------------
__global__ void pack_x_kernel(const float* __restrict__ x)
{
    __shared__ float st[64][65];
    int tc = blockIdx.x, cc = blockIdx.y, b = blockIdx.z, tid = threadIdx.x;
    for (int i = tid; i < 64 * 16; i += 256) {
        int c = i >> 4, q = i & 15;
        float4 v = *(const float4*)(x + ((size_t)(b * CHN + cc * 64 + c)) * TDIM + tc * 64 + q * 4);
        st[q*4+0][c] = v.x; st[q*4+1][c] = v.y; st[q*4+2][c] = v.z; st[q*4+3][c] = v.w;
    }
    __syncthreads();
    for (int i = tid; i < 64 * 32; i += 256) {
        int r = i >> 5, cp = (i & 31) * 2;
        __half h0 = __float2half_rn(st[r][cp]), h1 = __float2half_rn(st[r][cp + 1]);
        size_t go = ((size_t)b * 4104 + tc * 64 + 8 + r) * CHN + cc * 64 + cp;
        *(uint32_t*)(g_x + go) = ((uint32_t)__half_as_ushort(h1) << 16) | __half_as_ushort(h0);
    }
    if (tc == 0)
        for (int i = tid; i < 8 * 32; i += 256) {
            int r = i >> 5, cp = (i & 31) * 2;
            *(uint32_t*)(g_x + ((size_t)b * 4104 + r) * CHN + cc * 64 + cp) = 0;
        }
}

// ---------------------------------------------------------------------------
// GEMM: C[64 t][128 n] = A[t][K] * B[n][K]^T, single-pass fp16.
// PHASE 1: A=x image, K=512, epilogue tanh*sigmoid -> z plane.
// PHASE 2: A=z plane, K=256, epilogue bias (+x for res) -> out.
// 8 warps (2m x 4n), warp tile 32x32, 4-stage ring, 3 CTAs/SM.
// ---------------------------------------------------------------------------
template<int PHASE>
__global__ void __launch_bounds__(256, 3) gemm_tc(
    const float* __restrict__ x, const float* __restrict__ b0v,
    const float* __restrict__ b1v, float* __restrict__ out)
{
    extern __shared__ unsigned char smraw[];
    const uint32_t sb = smem_u32(smraw);
    const int tid = threadIdx.x, lane = tid & 31, wid = tid >> 5;
    const int wm = wid & 1, wn = wid >> 1;
    const int tt = blockIdx.x, nb = blockIdx.y, b = blockIdx.z;
    const int t0 = tt * 64;
    const int NK  = (PHASE == 1) ? 16 : 8;
    const int KST = (PHASE == 1) ? 512 : 256;

    const __half* Ap = (PHASE == 1) ? g_x + (size_t)b * 4104 * CHN
                                    : g_z + (size_t)b * TDIM * CHN;
    const __half* Bw = (PHASE == 1) ? g_w1 + nb * 128 * 512 : g_w2 + nb * 128 * 256;

    float acc[2][4][4];
    #pragma unroll
    for (int mi = 0; mi < 2; mi++)
        #pragma unroll
        for (int ni = 0; ni < 4; ni++)
            #pragma unroll
            for (int j = 0; j < 4; j++) acc[mi][ni][j] = 0.0f;

    auto load_stage = [&](int kc, int stg) {
        int koff = (PHASE == 1 && kc < 8) ? 8 : 0;
        int acol = (PHASE == 1) ? (kc & 7) * 32 : kc * 32;
        uint32_t sbase = sb + stg * STG;
        #pragma unroll
        for (int i = 0; i < 3; i++) {
            int idx = tid + i * 256;
            if (idx < 256) {
                int r = idx >> 2, seg = idx & 3;
                const __half* asrc = Ap + (size_t)(t0 + r + koff) * CHN + acol + seg * 8;
                cp16(sbase + r * 80 + seg * 16, asrc);
            } else {
                int j = idx - 256;
                int r = j >> 2, seg = j & 3;
                const __half* bsrc = Bw + (size_t)r * KST + kc * 32 + seg * 8;
                cp16(sbase + ASTG + r * 80 + seg * 16, bsrc);
            }
        }
        asm volatile("cp.async.commit_group;" ::: "memory");
    };

    load_stage(0, 0);
    load_stage(1, 1);
    load_stage(2, 2);

    int stg = 0;
    for (int kc = 0; kc < NK; kc++) {
        int rem = NK - 1 - kc;
        if (rem >= 2)      asm volatile("cp.async.wait_group 2;" ::: "memory");
        else if (rem == 1) asm volatile("cp.async.wait_group 1;" ::: "memory");
        else               asm volatile("cp.async.wait_group 0;" ::: "memory");
        __syncthreads();

        if (kc + 3 < NK) {
            int nstg = stg + 3; if (nstg >= NSTG) nstg -= NSTG;
            load_stage(kc + 3, nstg);
        }

        const uint32_t abase = sb + stg * STG;
        const uint32_t bbase = abase + ASTG;
        #pragma unroll
        for (int ks = 0; ks < 2; ks++) {
            uint32_t ah[2][4], bf2[4][2];
            const int arow = lane & 15, acoll = ks * 16 + (lane >> 4) * 8;
            const int brow = (lane & 7) + ((lane >> 4) << 3);
            const int bcol = ks * 16 + ((lane >> 3) & 1) * 8;
            #pragma unroll
            for (int ni2 = 0; ni2 < 2; ni2++) {
                uint32_t t4[4];
                ldmx4(t4, bbase + (wn * 32 + ni2 * 16 + brow) * 80 + bcol * 2);
                bf2[ni2*2][0] = t4[0]; bf2[ni2*2][1] = t4[1];
                bf2[ni2*2+1][0] = t4[2]; bf2[ni2*2+1][1] = t4[3];
            }
            #pragma unroll
            for (int mi = 0; mi < 2; mi++)
                ldmx4(ah[mi], abase + (wm * 32 + mi * 16 + arow) * 80 + acoll * 2);
            #pragma unroll
            for (int mi = 0; mi < 2; mi++)
                #pragma unroll
                for (int ni = 0; ni < 4; ni++)
                    mma_h(acc[mi][ni], ah[mi], bf2[ni]);
        }
        stg++; if (stg >= NSTG) stg = 0;
    }
    __syncthreads();

    // ---- stage C through smem [128 n][68 m] ----
    float* Cs = (float*)smraw;
    {
        const int tr = lane >> 2, tc4 = (lane & 3) * 2;
        #pragma unroll
        for (int mi = 0; mi < 2; mi++)
            #pragma unroll
            for (int ni = 0; ni < 4; ni++) {
                int n0 = wn * 32 + ni * 8 + tc4;
                int m0 = wm * 32 + mi * 16 + tr;
                Cs[n0 * 68 + m0]          = acc[mi][ni][0];
                Cs[(n0 + 1) * 68 + m0]    = acc[mi][ni][1];
                Cs[n0 * 68 + m0 + 8]      = acc[mi][ni][2];
                Cs[(n0 + 1) * 68 + m0 + 8] = acc[mi][ni][3];
            }
    }
    __syncthreads();

    if (PHASE == 1) {
        for (int i = tid; i < 64 * 32; i += 256) {
            int m = i >> 5, cp = (i & 31) * 2;
            float f0 = Cs[cp * 68 + m]        + __ldg(b0v + nb * 64 + cp);
            float f1 = Cs[(cp + 1) * 68 + m]  + __ldg(b0v + nb * 64 + cp + 1);
            float g0 = Cs[(64 + cp) * 68 + m] + __ldg(b1v + nb * 64 + cp);
            float g1 = Cs[(65 + cp) * 68 + m] + __ldg(b1v + nb * 64 + cp + 1);
            __half h0 = __float2half_rn(gatedact(f0, g0));
            __half h1 = __float2half_rn(gatedact(f1, g1));
            size_t go = ((size_t)(b * TDIM + t0 + m)) * CHN + nb * 64 + cp;
            *(uint32_t*)(g_z + go) = ((uint32_t)__half_as_ushort(h1) << 16) | __half_as_ushort(h0);
        }
    } else {
        for (int i = tid; i < 128 * 16; i += 256) {
            int c1 = i >> 4, mp = (i & 15) * 4;
            size_t go = ((size_t)(b * CHN + nb * 64 + ((c1 < 64) ? c1 : c1 - 64))) * TDIM + t0 + mp;
            if (c1 < 64) {
                float bias = __ldg(b0v + nb * 64 + c1);
                float4 xv = *(const float4*)(x + go);
                float4 v = make_float4(Cs[c1*68+mp]   + bias + xv.x,
                                       Cs[c1*68+mp+1] + bias + xv.y,
                                       Cs[c1*68+mp+2] + bias + xv.z,
                                       Cs[c1*68+mp+3] + bias + xv.w);
                *(float4*)(out + go) = v;
            } else {
                float bias = __ldg(b1v + nb * 64 + (c1 - 64));
                float4 v = make_float4(Cs[c1*68+mp]   + bias,
                                       Cs[c1*68+mp+1] + bias,
                                       Cs[c1*68+mp+2] + bias,
                                       Cs[c1*68+mp+3] + bias);
                *(float4*)(out + SKIPOFF + go) = v;
            }
        }
    }
}

// ---------------------------------------------------------------------------
extern "C" void kernel_launch(void* const* d_in, const int* in_sizes, int n_in,
                              void* d_out, int out_size)
{
    const float* x   = (const float*)d_in[0];
    const float* wf  = (const float*)d_in[1];
    const float* bf  = (const float*)d_in[2];
    const float* wg  = (const float*)d_in[3];
    const float* bg  = (const float*)d_in[4];
    const float* wr  = (const float*)d_in[5];
    const float* br  = (const float*)d_in[6];
    const float* wsk = (const float*)d_in[7];
    const float* bsk = (const float*)d_in[8];
    float* out = (float*)d_out;

    cudaFuncSetAttribute(gemm_tc<1>, cudaFuncAttributeMaxDynamicSharedMemorySize, SMEM_SZ);
    cudaFuncSetAttribute(gemm_tc<2>, cudaFuncAttributeMaxDynamicSharedMemorySize, SMEM_SZ);

    pack_w_kernel<<<1536, 256>>>(wf, wg, wr, wsk);
    pack_x_kernel<<<dim3(64, 4, BATCH), 256>>>(x);
    dim3 grid(64, 4, BATCH);
    gemm_tc<1><<<grid, 256, SMEM_SZ>>>(x, bf, bg, out);
    gemm_tc<2><<<grid, 256, SMEM_SZ>>>(x, br, bsk, out);
}